// round 10
// baseline (speedup 1.0000x reference)
#include <cuda_runtime.h>
#include <cuda_fp16.h>
#include <cstdint>

#define NN 100000
#define NE 3200000
#define HID 64
#define SCAN_B 512
#define NBLK1 ((NN + SCAN_B - 1) / SCAN_B)   // 196
#define TILE2 128
#define NT2 ((NN + TILE2 - 1) / TILE2)       // 782
#define HS_STRIDE 66                          // halves; conflict-free staging
#define ST_AGG  (1 << 28)
#define ST_PRE  (2 << 28)
#define VMASK   0x0FFFFFFF

// ---------------- scratch (device globals; no allocation) ----------------
__device__ int            g_cnt[NN];
__device__ float          g_dinv[NN];
__device__ float2         g_q[NN];         // q = dinv * x (layer-1 gather table)
__device__ int            g_row[NN + 1];   // CSR row pointers (by dst)
__device__ unsigned short g_slot[NE];      // within-bucket slot per edge (deg << 65536)
__device__ int            g_sorted[NE];    // src ids sorted by dst
__device__ __half2        g_ph[NN * 32];   // p = dinv*relu(h1), fp16, 128 B/node
__device__ float          g_pool[HID];
__device__ int            g_part[NBLK1];   // lookback: status<<28 | value
__device__ int            g_done;
__device__ int            g_flag;          // 1 = edge_index stored as int64

// ---------------- kernels ----------------

// zero counters/pool/lookback state; thread 0 detects int64 vs int32.
__global__ void k_init(const unsigned long long* __restrict__ e64) {
    int i = blockIdx.x * blockDim.x + threadIdx.x;
    if (i < NN) g_cnt[i] = 0;
    if (i < HID) g_pool[i] = 0.0f;
    if (i < NBLK1) g_part[i] = 0;
    if (i == 0) {
        g_done = 0;
        int is64 = 1;
        #pragma unroll
        for (int k = 0; k < 8; k++)
            if (e64[k] >= (unsigned long long)NN) { is64 = 0; break; }
        g_flag = is64;
    }
}

// Histogram dst AND record each edge's slot (ushort). 4 edges/thread.
__global__ void k_count(const void* __restrict__ edges) {
    int e0 = (blockIdx.x * blockDim.x + threadIdx.x) * 4;
    if (e0 >= NE) return;
    int d[4];
    if (g_flag) {
        const longlong2* d2 = (const longlong2*)((const long long*)edges + NE);
        longlong2 a = d2[e0 >> 1], b = d2[(e0 >> 1) + 1];
        d[0] = (int)a.x; d[1] = (int)a.y; d[2] = (int)b.x; d[3] = (int)b.y;
    } else {
        const int4* d4 = (const int4*)((const int*)edges + NE);
        int4 a = d4[e0 >> 2];
        d[0] = a.x; d[1] = a.y; d[2] = a.z; d[3] = a.w;
    }
    ushort4 sl;
    sl.x = (unsigned short)atomicAdd(&g_cnt[d[0]], 1);
    sl.y = (unsigned short)atomicAdd(&g_cnt[d[1]], 1);
    sl.z = (unsigned short)atomicAdd(&g_cnt[d[2]], 1);
    sl.w = (unsigned short)atomicAdd(&g_cnt[d[3]], 1);
    *(ushort4*)&g_slot[e0] = sl;
}

// Single-kernel exclusive scan (decoupled lookback) + dinv + q tables.
__global__ void __launch_bounds__(SCAN_B) k_scan(const float2* __restrict__ x2) {
    __shared__ int wsum[SCAN_B / 32];
    __shared__ int sh_total, sh_base;
    int bid = blockIdx.x, t = threadIdx.x;
    int i = bid * SCAN_B + t;
    int lane = t & 31, w = t >> 5;

    int v = (i < NN) ? g_cnt[i] : 0;
    int s = v;
    #pragma unroll
    for (int o = 1; o < 32; o <<= 1) {
        int u = __shfl_up_sync(0xffffffffu, s, o);
        if (lane >= o) s += u;
    }
    if (lane == 31) wsum[w] = s;
    __syncthreads();
    if (w == 0) {
        int ws = (lane < SCAN_B / 32) ? wsum[lane] : 0;
        #pragma unroll
        for (int o = 1; o < 16; o <<= 1) {
            int u = __shfl_up_sync(0xffffffffu, ws, o);
            if (lane >= o) ws += u;
        }
        if (lane < SCAN_B / 32) wsum[lane] = ws;
    }
    __syncthreads();
    int base_l = (w > 0) ? wsum[w - 1] : 0;
    int incl = s + base_l;                 // inclusive within block
    if (t == SCAN_B - 1) sh_total = incl;
    __syncthreads();
    int total = sh_total;

    if (t == 0) {
        int pk = (bid == 0) ? (ST_PRE | total) : (ST_AGG | total);
        *(volatile int*)&g_part[bid] = pk;
        __threadfence();
    }

    if (bid == 0) {
        if (t == 0) sh_base = 0;
    } else if (w == 0) {
        int run = 0, lag = 1;
        for (;;) {
            int idx = bid - lag - lane;
            int pv = (idx >= 0) ? *(volatile int*)&g_part[idx] : ST_PRE;
            if (!__all_sync(0xffffffffu, (pv & ~VMASK) != 0)) continue;
            unsigned pm = __ballot_sync(0xffffffffu, (pv & ~VMASK) == ST_PRE);
            int val = pv & VMASK;
            if (pm) {
                int pl = __ffs(pm) - 1;
                int c = (lane <= pl) ? val : 0;
                #pragma unroll
                for (int o = 16; o > 0; o >>= 1) c += __shfl_xor_sync(0xffffffffu, c, o);
                run += c;
                break;
            } else {
                int c = val;
                #pragma unroll
                for (int o = 16; o > 0; o >>= 1) c += __shfl_xor_sync(0xffffffffu, c, o);
                run += c;
                lag += 32;
            }
        }
        if (lane == 0) {
            *(volatile int*)&g_part[bid] = ST_PRE | ((run + total) & VMASK);
            __threadfence();
            sh_base = run;
        }
    }
    __syncthreads();
    int base_g = sh_base;

    if (i < NN) {
        g_row[i] = base_g + incl - v;      // exclusive global prefix
        float d = rsqrtf((float)v + 1.0f);
        g_dinv[i] = d;
        float2 xv = x2[i];
        g_q[i] = make_float2(xv.x * d, xv.y * d);
    }
    if (bid == 0 && t == 0) g_row[NN] = NE;
}

// Atomic-free counting-sort scatter: addr = row[dst] + slot[e]. 4 edges/thread.
__global__ void k_scatter(const void* __restrict__ edges) {
    int e0 = (blockIdx.x * blockDim.x + threadIdx.x) * 4;
    if (e0 >= NE) return;
    int s[4], d[4];
    if (g_flag) {
        const longlong2* sp = (const longlong2*)edges;
        const longlong2* dp = (const longlong2*)((const long long*)edges + NE);
        longlong2 sa = sp[e0 >> 1], sb = sp[(e0 >> 1) + 1];
        longlong2 da = dp[e0 >> 1], db = dp[(e0 >> 1) + 1];
        s[0] = (int)sa.x; s[1] = (int)sa.y; s[2] = (int)sb.x; s[3] = (int)sb.y;
        d[0] = (int)da.x; d[1] = (int)da.y; d[2] = (int)db.x; d[3] = (int)db.y;
    } else {
        const int4* sp = (const int4*)edges;
        const int4* dp = (const int4*)((const int*)edges + NE);
        int4 sa = sp[e0 >> 2], da = dp[e0 >> 2];
        s[0] = sa.x; s[1] = sa.y; s[2] = sa.z; s[3] = sa.w;
        d[0] = da.x; d[1] = da.y; d[2] = da.z; d[3] = da.w;
    }
    ushort4 sl = *(const ushort4*)&g_slot[e0];
    g_sorted[__ldg(&g_row[d[0]]) + sl.x] = s[0];
    g_sorted[__ldg(&g_row[d[1]]) + sl.y] = s[1];
    g_sorted[__ldg(&g_row[d[2]]) + sl.z] = s[2];
    g_sorted[__ldg(&g_row[d[3]]) + sl.w] = s[3];
}

// Warp-per-node: layer-1 CSR gather of q + 2->64 GEMV + relu -> fp16 p row.
__global__ void __launch_bounds__(256) k_h1p(const float* __restrict__ W1,
                                             const float* __restrict__ b1) {
    int gt = blockIdx.x * blockDim.x + threadIdx.x;
    int n = gt >> 5;
    if (n >= NN) return;
    int lane = gt & 31;

    int e0 = g_row[n], e1 = g_row[n + 1];
    float ax = 0.f, ay = 0.f;
    for (int e = e0 + lane; e < e1; e += 32) {
        float2 q = __ldg(&g_q[g_sorted[e]]);
        ax += q.x; ay += q.y;
    }
    #pragma unroll
    for (int o = 16; o > 0; o >>= 1) {
        ax += __shfl_xor_sync(0xffffffffu, ax, o);
        ay += __shfl_xor_sync(0xffffffffu, ay, o);
    }
    float2 qn = g_q[n];
    float dv = g_dinv[n];
    float xax = (ax + qn.x) * dv;
    float xay = (ay + qn.y) * dv;

    int f = 2 * lane;
    float v0 = fmaf(xax, __ldg(&W1[f]),     fmaf(xay, __ldg(&W1[HID + f]),     __ldg(&b1[f])));
    float v1 = fmaf(xax, __ldg(&W1[f + 1]), fmaf(xay, __ldg(&W1[HID + f + 1]), __ldg(&b1[f + 1])));
    v0 = fmaxf(v0, 0.0f) * dv;
    v1 = fmaxf(v1, 0.0f) * dv;
    g_ph[n * 32 + lane] = __floats2half2_rn(v0, v1);
}

// Fused: fp16 CSR gather (layer-2 agg) + node-batched h2 GEMV + relu + pool
// + (last block) final FC output.
// 256 threads: fg = tid&7 (8 feats), rg = tid>>3; thread handles nodes rg*4+i.
__global__ void __launch_bounds__(256) k_gather2(
        const float* __restrict__ W2, const float* __restrict__ b2,
        const float* __restrict__ Wfc, const float* __restrict__ bfc,
        float* __restrict__ out) {
    __shared__ float  W2s[HID * HID];             // 16 KB, [k*64 + f]
    __shared__ __half hs[TILE2 * HS_STRIDE];      // 16.9 KB
    __shared__ int    sh_last;

    int tid = threadIdx.x;
    int fg = tid & 7, rg = tid >> 3;

    for (int i = tid; i < HID * HID; i += 256) W2s[i] = W2[i];
    float bloc[8];
    #pragma unroll
    for (int j = 0; j < 8; j++) bloc[j] = __ldg(&b2[8 * fg + j]);
    __syncthreads();

    float pool8[8] = {0.f, 0.f, 0.f, 0.f, 0.f, 0.f, 0.f, 0.f};
    const uint4* pt = (const uint4*)g_ph;

    for (int tile = blockIdx.x; tile < NT2; tile += gridDim.x) {
        // -------- stage A: gather agg for 4 nodes, write fp16 to hs --------
        #pragma unroll
        for (int i = 0; i < 4; i++) {
            int nl = rg * 4 + i;
            int n = tile * TILE2 + nl;
            float acc[8] = {0.f, 0.f, 0.f, 0.f, 0.f, 0.f, 0.f, 0.f};
            if (n < NN) {
                int e0 = g_row[n], e1 = g_row[n + 1];
                __half2 pa[4][4];
                #pragma unroll
                for (int j = 0; j < 4; j++)
                    #pragma unroll
                    for (int k = 0; k < 4; k++)
                        pa[j][k] = __floats2half2_rn(0.f, 0.f);
                int e = e0;
                // align to 4 for int4 index loads
                for (; (e & 3) && e < e1; e++) {
                    int s = __ldg(&g_sorted[e]);
                    uint4 r = __ldg(&pt[s * 8 + fg]);
                    pa[0][0] = __hadd2(pa[0][0], *(__half2*)&r.x);
                    pa[0][1] = __hadd2(pa[0][1], *(__half2*)&r.y);
                    pa[0][2] = __hadd2(pa[0][2], *(__half2*)&r.z);
                    pa[0][3] = __hadd2(pa[0][3], *(__half2*)&r.w);
                }
                for (; e + 4 <= e1; e += 4) {
                    int4 s4 = __ldg((const int4*)&g_sorted[e]);
                    int sI[4] = {s4.x, s4.y, s4.z, s4.w};
                    #pragma unroll
                    for (int j = 0; j < 4; j++) {
                        uint4 r = __ldg(&pt[sI[j] * 8 + fg]);
                        pa[j][0] = __hadd2(pa[j][0], *(__half2*)&r.x);
                        pa[j][1] = __hadd2(pa[j][1], *(__half2*)&r.y);
                        pa[j][2] = __hadd2(pa[j][2], *(__half2*)&r.z);
                        pa[j][3] = __hadd2(pa[j][3], *(__half2*)&r.w);
                    }
                }
                for (; e < e1; e++) {
                    int s = __ldg(&g_sorted[e]);
                    uint4 r = __ldg(&pt[s * 8 + fg]);
                    pa[0][0] = __hadd2(pa[0][0], *(__half2*)&r.x);
                    pa[0][1] = __hadd2(pa[0][1], *(__half2*)&r.y);
                    pa[0][2] = __hadd2(pa[0][2], *(__half2*)&r.z);
                    pa[0][3] = __hadd2(pa[0][3], *(__half2*)&r.w);
                }
                #pragma unroll
                for (int j = 0; j < 4; j++) {
                    #pragma unroll
                    for (int k = 0; k < 4; k++) {
                        float2 f2 = __half22float2(pa[j][k]);
                        acc[2 * k]     += f2.x;
                        acc[2 * k + 1] += f2.y;
                    }
                }
                // self loop in fp32
                uint4 rs = pt[n * 8 + fg];
                float2 s0 = __half22float2(*(__half2*)&rs.x);
                float2 s1 = __half22float2(*(__half2*)&rs.y);
                float2 s2 = __half22float2(*(__half2*)&rs.z);
                float2 s3 = __half22float2(*(__half2*)&rs.w);
                acc[0] += s0.x; acc[1] += s0.y; acc[2] += s1.x; acc[3] += s1.y;
                acc[4] += s2.x; acc[5] += s2.y; acc[6] += s3.x; acc[7] += s3.y;
                float sc = g_dinv[n];
                #pragma unroll
                for (int k = 0; k < 8; k++) acc[k] *= sc;
            }
            __half2* hw = (__half2*)&hs[nl * HS_STRIDE + 8 * fg];
            #pragma unroll
            for (int j = 0; j < 4; j++)
                hw[j] = __floats2half2_rn(acc[2 * j], acc[2 * j + 1]);
        }
        __syncthreads();

        // -------- stage B: h2 GEMV for 4 nodes, W2 amortized 4x --------
        float o[4][8];
        #pragma unroll
        for (int i = 0; i < 4; i++)
            #pragma unroll
            for (int j = 0; j < 8; j++) o[i][j] = bloc[j];

        const __half* hp0 = &hs[(rg * 4 + 0) * HS_STRIDE];
        const __half* hp1 = &hs[(rg * 4 + 1) * HS_STRIDE];
        const __half* hp2 = &hs[(rg * 4 + 2) * HS_STRIDE];
        const __half* hp3 = &hs[(rg * 4 + 3) * HS_STRIDE];
        #pragma unroll 4
        for (int k = 0; k < HID; k++) {
            float a0 = __half2float(hp0[k]);
            float a1 = __half2float(hp1[k]);
            float a2 = __half2float(hp2[k]);
            float a3 = __half2float(hp3[k]);
            float4 wA = *(const float4*)&W2s[k * HID + 8 * fg];
            float4 wB = *(const float4*)&W2s[k * HID + 8 * fg + 4];
            o[0][0] = fmaf(a0, wA.x, o[0][0]); o[0][1] = fmaf(a0, wA.y, o[0][1]);
            o[0][2] = fmaf(a0, wA.z, o[0][2]); o[0][3] = fmaf(a0, wA.w, o[0][3]);
            o[0][4] = fmaf(a0, wB.x, o[0][4]); o[0][5] = fmaf(a0, wB.y, o[0][5]);
            o[0][6] = fmaf(a0, wB.z, o[0][6]); o[0][7] = fmaf(a0, wB.w, o[0][7]);
            o[1][0] = fmaf(a1, wA.x, o[1][0]); o[1][1] = fmaf(a1, wA.y, o[1][1]);
            o[1][2] = fmaf(a1, wA.z, o[1][2]); o[1][3] = fmaf(a1, wA.w, o[1][3]);
            o[1][4] = fmaf(a1, wB.x, o[1][4]); o[1][5] = fmaf(a1, wB.y, o[1][5]);
            o[1][6] = fmaf(a1, wB.z, o[1][6]); o[1][7] = fmaf(a1, wB.w, o[1][7]);
            o[2][0] = fmaf(a2, wA.x, o[2][0]); o[2][1] = fmaf(a2, wA.y, o[2][1]);
            o[2][2] = fmaf(a2, wA.z, o[2][2]); o[2][3] = fmaf(a2, wA.w, o[2][3]);
            o[2][4] = fmaf(a2, wB.x, o[2][4]); o[2][5] = fmaf(a2, wB.y, o[2][5]);
            o[2][6] = fmaf(a2, wB.z, o[2][6]); o[2][7] = fmaf(a2, wB.w, o[2][7]);
            o[3][0] = fmaf(a3, wA.x, o[3][0]); o[3][1] = fmaf(a3, wA.y, o[3][1]);
            o[3][2] = fmaf(a3, wA.z, o[3][2]); o[3][3] = fmaf(a3, wA.w, o[3][3]);
            o[3][4] = fmaf(a3, wB.x, o[3][4]); o[3][5] = fmaf(a3, wB.y, o[3][5]);
            o[3][6] = fmaf(a3, wB.z, o[3][6]); o[3][7] = fmaf(a3, wB.w, o[3][7]);
        }
        #pragma unroll
        for (int i = 0; i < 4; i++) {
            int n = tile * TILE2 + rg * 4 + i;
            if (n < NN) {
                #pragma unroll
                for (int j = 0; j < 8; j++)
                    pool8[j] += fmaxf(o[i][j], 0.f);
            }
        }
        __syncthreads();   // hs reused next tile
    }

    // -------- final pool reduction (reuse hs as float scratch) --------
    float* hsf = (float*)hs;   // 32*64 floats = 8 KB
    #pragma unroll
    for (int j = 0; j < 8; j++)
        hsf[rg * HID + 8 * fg + j] = pool8[j];
    __syncthreads();
    if (tid < HID) {
        float s = 0.f;
        #pragma unroll 8
        for (int r = 0; r < 32; r++) s += hsf[r * HID + tid];
        atomicAdd(&g_pool[tid], s);
    }

    // -------- last block computes the final FC output --------
    if (tid == 0) {
        __threadfence();
        int t = atomicAdd(&g_done, 1);
        sh_last = (t == gridDim.x - 1);
    }
    __syncthreads();
    if (sh_last && tid < 32) {
        float s = g_pool[tid] * __ldg(&Wfc[tid]) + g_pool[tid + 32] * __ldg(&Wfc[tid + 32]);
        #pragma unroll
        for (int o2 = 16; o2 > 0; o2 >>= 1) s += __shfl_down_sync(0xffffffffu, s, o2);
        if (tid == 0) out[0] = s * (1.0f / NN) + __ldg(&bfc[0]);
    }
}

// ---------------- launch ----------------
extern "C" void kernel_launch(void* const* d_in, const int* in_sizes, int n_in,
                              void* d_out, int out_size) {
    const float2* x2    = (const float2*)d_in[0];
    const void*   edges = d_in[1];
    const float*  W1    = (const float*)d_in[2];
    const float*  b1    = (const float*)d_in[3];
    const float*  W2    = (const float*)d_in[4];
    const float*  b2    = (const float*)d_in[5];
    const float*  Wfc   = (const float*)d_in[6];
    const float*  bfc   = (const float*)d_in[7];
    float* out = (float*)d_out;

    const int T = 256;
    k_init<<<(NN + T - 1) / T, T>>>((const unsigned long long*)edges);
    k_count<<<(NE / 4 + T - 1) / T, T>>>(edges);
    k_scan<<<NBLK1, SCAN_B>>>(x2);
    k_scatter<<<(NE / 4 + T - 1) / T, T>>>(edges);
    k_h1p<<<(NN * 32 + T - 1) / T, T>>>(W1, b1);
    k_gather2<<<NT2, T>>>(W2, b2, Wfc, bfc, out);
}

// round 11
// speedup vs baseline: 1.0457x; 1.0457x over previous
#include <cuda_runtime.h>
#include <cuda_fp16.h>
#include <cstdint>

#define NN 100000
#define NE 3200000
#define HID 64
#define SCAN_B 512
#define NBLK1 ((NN + SCAN_B - 1) / SCAN_B)   // 196
#define TILE2 128
#define NT2 ((NN + TILE2 - 1) / TILE2)       // 782
#define HS_STRIDE 66                          // halves; conflict-free staging
#define ST_AGG  (1 << 28)
#define ST_PRE  (2 << 28)
#define VMASK   0x0FFFFFFF

// ---------------- scratch (device globals; no allocation) ----------------
__device__ int            g_cnt[NN];
__device__ float          g_dinv[NN];
__device__ float2         g_q[NN];         // q = dinv * x (layer-1 gather table)
__device__ int            g_row[NN + 1];   // CSR row pointers (by dst)
__device__ unsigned short g_slot[NE];      // within-bucket slot per edge
__device__ int            g_sorted[NE];    // src ids sorted by dst
__device__ __half2        g_ph[NN * 32];   // p = dinv*relu(h1), fp16, 128 B/node
__device__ float          g_pool[HID];
__device__ int            g_part[NBLK1];   // lookback: status<<28 | value
__device__ int            g_done;
__device__ int            g_flag;          // 1 = edge_index stored as int64

// ---------------- kernels ----------------

// zero counters/pool/lookback state; thread 0 detects int64 vs int32.
__global__ void k_init(const unsigned long long* __restrict__ e64) {
    int i = blockIdx.x * blockDim.x + threadIdx.x;
    if (i < NN) g_cnt[i] = 0;
    if (i < HID) g_pool[i] = 0.0f;
    if (i < NBLK1) g_part[i] = 0;
    if (i == 0) {
        g_done = 0;
        int is64 = 1;
        #pragma unroll
        for (int k = 0; k < 8; k++)
            if (e64[k] >= (unsigned long long)NN) { is64 = 0; break; }
        g_flag = is64;
    }
}

// Histogram dst AND record each edge's slot (ushort). 4 edges/thread.
__global__ void k_count(const void* __restrict__ edges) {
    int e0 = (blockIdx.x * blockDim.x + threadIdx.x) * 4;
    if (e0 >= NE) return;
    int d[4];
    if (g_flag) {
        const longlong2* d2 = (const longlong2*)((const long long*)edges + NE);
        longlong2 a = d2[e0 >> 1], b = d2[(e0 >> 1) + 1];
        d[0] = (int)a.x; d[1] = (int)a.y; d[2] = (int)b.x; d[3] = (int)b.y;
    } else {
        const int4* d4 = (const int4*)((const int*)edges + NE);
        int4 a = d4[e0 >> 2];
        d[0] = a.x; d[1] = a.y; d[2] = a.z; d[3] = a.w;
    }
    ushort4 sl;
    sl.x = (unsigned short)atomicAdd(&g_cnt[d[0]], 1);
    sl.y = (unsigned short)atomicAdd(&g_cnt[d[1]], 1);
    sl.z = (unsigned short)atomicAdd(&g_cnt[d[2]], 1);
    sl.w = (unsigned short)atomicAdd(&g_cnt[d[3]], 1);
    *(ushort4*)&g_slot[e0] = sl;
}

// Single-kernel exclusive scan (decoupled lookback) + dinv + q tables.
__global__ void __launch_bounds__(SCAN_B) k_scan(const float2* __restrict__ x2) {
    __shared__ int wsum[SCAN_B / 32];
    __shared__ int sh_total, sh_base;
    int bid = blockIdx.x, t = threadIdx.x;
    int i = bid * SCAN_B + t;
    int lane = t & 31, w = t >> 5;

    int v = (i < NN) ? g_cnt[i] : 0;
    int s = v;
    #pragma unroll
    for (int o = 1; o < 32; o <<= 1) {
        int u = __shfl_up_sync(0xffffffffu, s, o);
        if (lane >= o) s += u;
    }
    if (lane == 31) wsum[w] = s;
    __syncthreads();
    if (w == 0) {
        int ws = (lane < SCAN_B / 32) ? wsum[lane] : 0;
        #pragma unroll
        for (int o = 1; o < 16; o <<= 1) {
            int u = __shfl_up_sync(0xffffffffu, ws, o);
            if (lane >= o) ws += u;
        }
        if (lane < SCAN_B / 32) wsum[lane] = ws;
    }
    __syncthreads();
    int base_l = (w > 0) ? wsum[w - 1] : 0;
    int incl = s + base_l;                 // inclusive within block
    if (t == SCAN_B - 1) sh_total = incl;
    __syncthreads();
    int total = sh_total;

    if (t == 0) {
        int pk = (bid == 0) ? (ST_PRE | total) : (ST_AGG | total);
        *(volatile int*)&g_part[bid] = pk;
        __threadfence();
    }

    if (bid == 0) {
        if (t == 0) sh_base = 0;
    } else if (w == 0) {
        int run = 0, lag = 1;
        for (;;) {
            int idx = bid - lag - lane;
            int pv = (idx >= 0) ? *(volatile int*)&g_part[idx] : ST_PRE;
            if (!__all_sync(0xffffffffu, (pv & ~VMASK) != 0)) continue;
            unsigned pm = __ballot_sync(0xffffffffu, (pv & ~VMASK) == ST_PRE);
            int val = pv & VMASK;
            if (pm) {
                int pl = __ffs(pm) - 1;
                int c = (lane <= pl) ? val : 0;
                #pragma unroll
                for (int o = 16; o > 0; o >>= 1) c += __shfl_xor_sync(0xffffffffu, c, o);
                run += c;
                break;
            } else {
                int c = val;
                #pragma unroll
                for (int o = 16; o > 0; o >>= 1) c += __shfl_xor_sync(0xffffffffu, c, o);
                run += c;
                lag += 32;
            }
        }
        if (lane == 0) {
            *(volatile int*)&g_part[bid] = ST_PRE | ((run + total) & VMASK);
            __threadfence();
            sh_base = run;
        }
    }
    __syncthreads();
    int base_g = sh_base;

    if (i < NN) {
        g_row[i] = base_g + incl - v;      // exclusive global prefix
        float d = rsqrtf((float)v + 1.0f);
        g_dinv[i] = d;
        float2 xv = x2[i];
        g_q[i] = make_float2(xv.x * d, xv.y * d);
    }
    if (bid == 0 && t == 0) g_row[NN] = NE;
}

// Atomic-free counting-sort scatter: addr = row[dst] + slot[e]. 4 edges/thread.
__global__ void k_scatter(const void* __restrict__ edges) {
    int e0 = (blockIdx.x * blockDim.x + threadIdx.x) * 4;
    if (e0 >= NE) return;
    int s[4], d[4];
    if (g_flag) {
        const longlong2* sp = (const longlong2*)edges;
        const longlong2* dp = (const longlong2*)((const long long*)edges + NE);
        longlong2 sa = sp[e0 >> 1], sb = sp[(e0 >> 1) + 1];
        longlong2 da = dp[e0 >> 1], db = dp[(e0 >> 1) + 1];
        s[0] = (int)sa.x; s[1] = (int)sa.y; s[2] = (int)sb.x; s[3] = (int)sb.y;
        d[0] = (int)da.x; d[1] = (int)da.y; d[2] = (int)db.x; d[3] = (int)db.y;
    } else {
        const int4* sp = (const int4*)edges;
        const int4* dp = (const int4*)((const int*)edges + NE);
        int4 sa = sp[e0 >> 2], da = dp[e0 >> 2];
        s[0] = sa.x; s[1] = sa.y; s[2] = sa.z; s[3] = sa.w;
        d[0] = da.x; d[1] = da.y; d[2] = da.z; d[3] = da.w;
    }
    ushort4 sl = *(const ushort4*)&g_slot[e0];
    g_sorted[__ldg(&g_row[d[0]]) + sl.x] = s[0];
    g_sorted[__ldg(&g_row[d[1]]) + sl.y] = s[1];
    g_sorted[__ldg(&g_row[d[2]]) + sl.z] = s[2];
    g_sorted[__ldg(&g_row[d[3]]) + sl.w] = s[3];
}

// Warp-per-node: layer-1 CSR gather of q + 2->64 GEMV + relu -> fp16 p row.
__global__ void __launch_bounds__(256) k_h1p(const float* __restrict__ W1,
                                             const float* __restrict__ b1) {
    int gt = blockIdx.x * blockDim.x + threadIdx.x;
    int n = gt >> 5;
    if (n >= NN) return;
    int lane = gt & 31;

    int e0 = g_row[n], e1 = g_row[n + 1];
    float ax = 0.f, ay = 0.f;
    for (int e = e0 + lane; e < e1; e += 32) {
        float2 q = __ldg(&g_q[g_sorted[e]]);
        ax += q.x; ay += q.y;
    }
    #pragma unroll
    for (int o = 16; o > 0; o >>= 1) {
        ax += __shfl_xor_sync(0xffffffffu, ax, o);
        ay += __shfl_xor_sync(0xffffffffu, ay, o);
    }
    float2 qn = g_q[n];
    float dv = g_dinv[n];
    float xax = (ax + qn.x) * dv;
    float xay = (ay + qn.y) * dv;

    int f = 2 * lane;
    float v0 = fmaf(xax, __ldg(&W1[f]),     fmaf(xay, __ldg(&W1[HID + f]),     __ldg(&b1[f])));
    float v1 = fmaf(xax, __ldg(&W1[f + 1]), fmaf(xay, __ldg(&W1[HID + f + 1]), __ldg(&b1[f + 1])));
    v0 = fmaxf(v0, 0.0f) * dv;
    v1 = fmaxf(v1, 0.0f) * dv;
    g_ph[n * 32 + lane] = __floats2half2_rn(v0, v1);
}

// Fused: fp16 CSR gather (layer-2 agg) + node-batched h2 GEMV + relu + pool
// + (last block) final FC output.
// 256 threads: fg = tid&7 (8 feats), rg = tid>>3; thread handles nodes rg*4+i.
__global__ void __launch_bounds__(256) k_gather2(
        const float* __restrict__ W2, const float* __restrict__ b2,
        const float* __restrict__ Wfc, const float* __restrict__ bfc,
        float* __restrict__ out) {
    __shared__ float  W2s[HID * HID];             // 16 KB, [k*64 + f]
    __shared__ __half hs[TILE2 * HS_STRIDE];      // 16.9 KB
    __shared__ int    sh_last;

    int tid = threadIdx.x;
    int fg = tid & 7, rg = tid >> 3;

    for (int i = tid; i < HID * HID; i += 256) W2s[i] = W2[i];
    float bloc[8];
    #pragma unroll
    for (int j = 0; j < 8; j++) bloc[j] = __ldg(&b2[8 * fg + j]);
    __syncthreads();

    float pool8[8] = {0.f, 0.f, 0.f, 0.f, 0.f, 0.f, 0.f, 0.f};
    const uint4* pt = (const uint4*)g_ph;

    for (int tile = blockIdx.x; tile < NT2; tile += gridDim.x) {
        // -------- stage A: gather agg for 4 nodes, write fp16 to hs --------
        #pragma unroll
        for (int i = 0; i < 4; i++) {
            int nl = rg * 4 + i;
            int n = tile * TILE2 + nl;
            float acc[8] = {0.f, 0.f, 0.f, 0.f, 0.f, 0.f, 0.f, 0.f};
            if (n < NN) {
                int e0 = g_row[n], e1 = g_row[n + 1];
                __half2 pa[4][4];
                #pragma unroll
                for (int j = 0; j < 4; j++)
                    #pragma unroll
                    for (int k = 0; k < 4; k++)
                        pa[j][k] = __floats2half2_rn(0.f, 0.f);
                int e = e0;
                // 8-deep MLP: batch 8 index loads, 8 row loads, then accumulate
                for (; e + 8 <= e1; e += 8) {
                    int sI[8];
                    uint4 r[8];
                    #pragma unroll
                    for (int u = 0; u < 8; u++) sI[u] = __ldg(&g_sorted[e + u]);
                    #pragma unroll
                    for (int u = 0; u < 8; u++) r[u] = __ldg(&pt[sI[u] * 8 + fg]);
                    #pragma unroll
                    for (int u = 0; u < 8; u++) {
                        pa[u & 3][0] = __hadd2(pa[u & 3][0], *(__half2*)&r[u].x);
                        pa[u & 3][1] = __hadd2(pa[u & 3][1], *(__half2*)&r[u].y);
                        pa[u & 3][2] = __hadd2(pa[u & 3][2], *(__half2*)&r[u].z);
                        pa[u & 3][3] = __hadd2(pa[u & 3][3], *(__half2*)&r[u].w);
                    }
                }
                for (; e + 4 <= e1; e += 4) {
                    #pragma unroll
                    for (int u = 0; u < 4; u++) {
                        int sv = __ldg(&g_sorted[e + u]);
                        uint4 r = __ldg(&pt[sv * 8 + fg]);
                        pa[u][0] = __hadd2(pa[u][0], *(__half2*)&r.x);
                        pa[u][1] = __hadd2(pa[u][1], *(__half2*)&r.y);
                        pa[u][2] = __hadd2(pa[u][2], *(__half2*)&r.z);
                        pa[u][3] = __hadd2(pa[u][3], *(__half2*)&r.w);
                    }
                }
                for (; e < e1; e++) {
                    int sv = __ldg(&g_sorted[e]);
                    uint4 r = __ldg(&pt[sv * 8 + fg]);
                    pa[0][0] = __hadd2(pa[0][0], *(__half2*)&r.x);
                    pa[0][1] = __hadd2(pa[0][1], *(__half2*)&r.y);
                    pa[0][2] = __hadd2(pa[0][2], *(__half2*)&r.z);
                    pa[0][3] = __hadd2(pa[0][3], *(__half2*)&r.w);
                }
                #pragma unroll
                for (int j = 0; j < 4; j++) {
                    #pragma unroll
                    for (int k = 0; k < 4; k++) {
                        float2 f2 = __half22float2(pa[j][k]);
                        acc[2 * k]     += f2.x;
                        acc[2 * k + 1] += f2.y;
                    }
                }
                // self loop in fp32
                uint4 rs = pt[n * 8 + fg];
                float2 s0 = __half22float2(*(__half2*)&rs.x);
                float2 s1 = __half22float2(*(__half2*)&rs.y);
                float2 s2 = __half22float2(*(__half2*)&rs.z);
                float2 s3 = __half22float2(*(__half2*)&rs.w);
                acc[0] += s0.x; acc[1] += s0.y; acc[2] += s1.x; acc[3] += s1.y;
                acc[4] += s2.x; acc[5] += s2.y; acc[6] += s3.x; acc[7] += s3.y;
                float sc = g_dinv[n];
                #pragma unroll
                for (int k = 0; k < 8; k++) acc[k] *= sc;
            }
            __half2* hw = (__half2*)&hs[nl * HS_STRIDE + 8 * fg];
            #pragma unroll
            for (int j = 0; j < 4; j++)
                hw[j] = __floats2half2_rn(acc[2 * j], acc[2 * j + 1]);
        }
        __syncthreads();

        // -------- stage B: h2 GEMV for 4 nodes, W2 amortized 4x --------
        float o[4][8];
        #pragma unroll
        for (int i = 0; i < 4; i++)
            #pragma unroll
            for (int j = 0; j < 8; j++) o[i][j] = bloc[j];

        const __half* hp0 = &hs[(rg * 4 + 0) * HS_STRIDE];
        const __half* hp1 = &hs[(rg * 4 + 1) * HS_STRIDE];
        const __half* hp2 = &hs[(rg * 4 + 2) * HS_STRIDE];
        const __half* hp3 = &hs[(rg * 4 + 3) * HS_STRIDE];
        #pragma unroll 4
        for (int k = 0; k < HID; k++) {
            float a0 = __half2float(hp0[k]);
            float a1 = __half2float(hp1[k]);
            float a2 = __half2float(hp2[k]);
            float a3 = __half2float(hp3[k]);
            float4 wA = *(const float4*)&W2s[k * HID + 8 * fg];
            float4 wB = *(const float4*)&W2s[k * HID + 8 * fg + 4];
            o[0][0] = fmaf(a0, wA.x, o[0][0]); o[0][1] = fmaf(a0, wA.y, o[0][1]);
            o[0][2] = fmaf(a0, wA.z, o[0][2]); o[0][3] = fmaf(a0, wA.w, o[0][3]);
            o[0][4] = fmaf(a0, wB.x, o[0][4]); o[0][5] = fmaf(a0, wB.y, o[0][5]);
            o[0][6] = fmaf(a0, wB.z, o[0][6]); o[0][7] = fmaf(a0, wB.w, o[0][7]);
            o[1][0] = fmaf(a1, wA.x, o[1][0]); o[1][1] = fmaf(a1, wA.y, o[1][1]);
            o[1][2] = fmaf(a1, wA.z, o[1][2]); o[1][3] = fmaf(a1, wA.w, o[1][3]);
            o[1][4] = fmaf(a1, wB.x, o[1][4]); o[1][5] = fmaf(a1, wB.y, o[1][5]);
            o[1][6] = fmaf(a1, wB.z, o[1][6]); o[1][7] = fmaf(a1, wB.w, o[1][7]);
            o[2][0] = fmaf(a2, wA.x, o[2][0]); o[2][1] = fmaf(a2, wA.y, o[2][1]);
            o[2][2] = fmaf(a2, wA.z, o[2][2]); o[2][3] = fmaf(a2, wA.w, o[2][3]);
            o[2][4] = fmaf(a2, wB.x, o[2][4]); o[2][5] = fmaf(a2, wB.y, o[2][5]);
            o[2][6] = fmaf(a2, wB.z, o[2][6]); o[2][7] = fmaf(a2, wB.w, o[2][7]);
            o[3][0] = fmaf(a3, wA.x, o[3][0]); o[3][1] = fmaf(a3, wA.y, o[3][1]);
            o[3][2] = fmaf(a3, wA.z, o[3][2]); o[3][3] = fmaf(a3, wA.w, o[3][3]);
            o[3][4] = fmaf(a3, wB.x, o[3][4]); o[3][5] = fmaf(a3, wB.y, o[3][5]);
            o[3][6] = fmaf(a3, wB.z, o[3][6]); o[3][7] = fmaf(a3, wB.w, o[3][7]);
        }
        #pragma unroll
        for (int i = 0; i < 4; i++) {
            int n = tile * TILE2 + rg * 4 + i;
            if (n < NN) {
                #pragma unroll
                for (int j = 0; j < 8; j++)
                    pool8[j] += fmaxf(o[i][j], 0.f);
            }
        }
        __syncthreads();   // hs reused next tile
    }

    // -------- final pool reduction (reuse hs as float scratch) --------
    float* hsf = (float*)hs;   // 32*64 floats = 8 KB
    #pragma unroll
    for (int j = 0; j < 8; j++)
        hsf[rg * HID + 8 * fg + j] = pool8[j];
    __syncthreads();
    if (tid < HID) {
        float s = 0.f;
        #pragma unroll 8
        for (int r = 0; r < 32; r++) s += hsf[r * HID + tid];
        atomicAdd(&g_pool[tid], s);
    }

    // -------- last block computes the final FC output --------
    if (tid == 0) {
        __threadfence();
        int t = atomicAdd(&g_done, 1);
        sh_last = (t == gridDim.x - 1);
    }
    __syncthreads();
    if (sh_last && tid < 32) {
        float s = g_pool[tid] * __ldg(&Wfc[tid]) + g_pool[tid + 32] * __ldg(&Wfc[tid + 32]);
        #pragma unroll
        for (int o2 = 16; o2 > 0; o2 >>= 1) s += __shfl_down_sync(0xffffffffu, s, o2);
        if (tid == 0) out[0] = s * (1.0f / NN) + __ldg(&bfc[0]);
    }
}

// ---------------- launch ----------------
extern "C" void kernel_launch(void* const* d_in, const int* in_sizes, int n_in,
                              void* d_out, int out_size) {
    const float2* x2    = (const float2*)d_in[0];
    const void*   edges = d_in[1];
    const float*  W1    = (const float*)d_in[2];
    const float*  b1    = (const float*)d_in[3];
    const float*  W2    = (const float*)d_in[4];
    const float*  b2    = (const float*)d_in[5];
    const float*  Wfc   = (const float*)d_in[6];
    const float*  bfc   = (const float*)d_in[7];
    float* out = (float*)d_out;

    const int T = 256;
    k_init<<<(NN + T - 1) / T, T>>>((const unsigned long long*)edges);
    k_count<<<(NE / 4 + T - 1) / T, T>>>(edges);
    k_scan<<<NBLK1, SCAN_B>>>(x2);
    k_scatter<<<(NE / 4 + T - 1) / T, T>>>(edges);
    k_h1p<<<(NN * 32 + T - 1) / T, T>>>(W1, b1);
    k_gather2<<<NT2, T>>>(W2, b2, Wfc, bfc, out);
}

// round 12
// speedup vs baseline: 1.0506x; 1.0046x over previous
#include <cuda_runtime.h>
#include <cuda_fp16.h>
#include <cstdint>

#define NN 100000
#define NE 3200000
#define HID 64
#define SCAN_B 512
#define NBLK1 ((NN + SCAN_B - 1) / SCAN_B)   // 196
#define TILE2 128
#define NT2 ((NN + TILE2 - 1) / TILE2)       // 782
#define HS_STRIDE 66                          // halves; conflict-free staging
#define ST_AGG  (1 << 28)
#define ST_PRE  (2 << 28)
#define VMASK   0x0FFFFFFF

// ---------------- scratch (device globals; zero-initialized at load) -------
// Pipeline is self-cleaning: every replay leaves these in the zeroed state
// the next replay expects (g_cnt by k_scan, g_part by k_scatter, g_pool and
// g_done by k_gather2's last block).
__device__ int            g_cnt[NN];
__device__ float          g_dinv[NN];
__device__ float2         g_q[NN];         // q = dinv * x (layer-1 gather table)
__device__ int            g_row[NN + 1];   // CSR row pointers (by dst)
__device__ unsigned short g_slot[NE];      // within-bucket slot per edge
__device__ int            g_sorted[NE];    // src ids sorted by dst
__device__ __half2        g_ph[NN * 32];   // p = dinv*relu(h1), fp16, 128 B/node
__device__ float          g_pool[HID];
__device__ int            g_part[NBLK1];   // lookback: status<<28 | value
__device__ int            g_done;

// Detect int64 vs int32 storage from the first 8 qwords (prob. of false
// int64-positive on int32 data ~ (1e5/2^63)^8 ~ 0).
__device__ __forceinline__ int detect_is64(const void* edges) {
    const unsigned long long* e64 = (const unsigned long long*)edges;
    int is64 = 1;
    #pragma unroll
    for (int k = 0; k < 8; k++)
        if (e64[k] >= (unsigned long long)NN) { is64 = 0; break; }
    return is64;
}

// ---------------- kernels ----------------

// Histogram dst AND record each edge's slot (ushort). 4 edges/thread.
__global__ void k_count(const void* __restrict__ edges) {
    __shared__ int sh_is64;
    if (threadIdx.x == 0) sh_is64 = detect_is64(edges);
    __syncthreads();
    int e0 = (blockIdx.x * blockDim.x + threadIdx.x) * 4;
    if (e0 >= NE) return;
    int d[4];
    if (sh_is64) {
        const longlong2* d2 = (const longlong2*)((const long long*)edges + NE);
        longlong2 a = d2[e0 >> 1], b = d2[(e0 >> 1) + 1];
        d[0] = (int)a.x; d[1] = (int)a.y; d[2] = (int)b.x; d[3] = (int)b.y;
    } else {
        const int4* d4 = (const int4*)((const int*)edges + NE);
        int4 a = d4[e0 >> 2];
        d[0] = a.x; d[1] = a.y; d[2] = a.z; d[3] = a.w;
    }
    ushort4 sl;
    sl.x = (unsigned short)atomicAdd(&g_cnt[d[0]], 1);
    sl.y = (unsigned short)atomicAdd(&g_cnt[d[1]], 1);
    sl.z = (unsigned short)atomicAdd(&g_cnt[d[2]], 1);
    sl.w = (unsigned short)atomicAdd(&g_cnt[d[3]], 1);
    *(ushort4*)&g_slot[e0] = sl;
}

// Single-kernel exclusive scan (decoupled lookback) + dinv + q tables.
// Also re-zeros g_cnt for the next graph replay.
__global__ void __launch_bounds__(SCAN_B) k_scan(const float2* __restrict__ x2) {
    __shared__ int wsum[SCAN_B / 32];
    __shared__ int sh_total, sh_base;
    int bid = blockIdx.x, t = threadIdx.x;
    int i = bid * SCAN_B + t;
    int lane = t & 31, w = t >> 5;

    int v = (i < NN) ? g_cnt[i] : 0;
    int s = v;
    #pragma unroll
    for (int o = 1; o < 32; o <<= 1) {
        int u = __shfl_up_sync(0xffffffffu, s, o);
        if (lane >= o) s += u;
    }
    if (lane == 31) wsum[w] = s;
    __syncthreads();
    if (w == 0) {
        int ws = (lane < SCAN_B / 32) ? wsum[lane] : 0;
        #pragma unroll
        for (int o = 1; o < 16; o <<= 1) {
            int u = __shfl_up_sync(0xffffffffu, ws, o);
            if (lane >= o) ws += u;
        }
        if (lane < SCAN_B / 32) wsum[lane] = ws;
    }
    __syncthreads();
    int base_l = (w > 0) ? wsum[w - 1] : 0;
    int incl = s + base_l;                 // inclusive within block
    if (t == SCAN_B - 1) sh_total = incl;
    __syncthreads();
    int total = sh_total;

    if (t == 0) {
        int pk = (bid == 0) ? (ST_PRE | total) : (ST_AGG | total);
        *(volatile int*)&g_part[bid] = pk;
        __threadfence();
    }

    if (bid == 0) {
        if (t == 0) sh_base = 0;
    } else if (w == 0) {
        int run = 0, lag = 1;
        for (;;) {
            int idx = bid - lag - lane;
            int pv = (idx >= 0) ? *(volatile int*)&g_part[idx] : ST_PRE;
            if (!__all_sync(0xffffffffu, (pv & ~VMASK) != 0)) continue;
            unsigned pm = __ballot_sync(0xffffffffu, (pv & ~VMASK) == ST_PRE);
            int val = pv & VMASK;
            if (pm) {
                int pl = __ffs(pm) - 1;
                int c = (lane <= pl) ? val : 0;
                #pragma unroll
                for (int o = 16; o > 0; o >>= 1) c += __shfl_xor_sync(0xffffffffu, c, o);
                run += c;
                break;
            } else {
                int c = val;
                #pragma unroll
                for (int o = 16; o > 0; o >>= 1) c += __shfl_xor_sync(0xffffffffu, c, o);
                run += c;
                lag += 32;
            }
        }
        if (lane == 0) {
            *(volatile int*)&g_part[bid] = ST_PRE | ((run + total) & VMASK);
            __threadfence();
            sh_base = run;
        }
    }
    __syncthreads();
    int base_g = sh_base;

    if (i < NN) {
        g_row[i] = base_g + incl - v;      // exclusive global prefix
        g_cnt[i] = 0;                      // self-clean for next replay
        float d = rsqrtf((float)v + 1.0f);
        g_dinv[i] = d;
        float2 xv = x2[i];
        g_q[i] = make_float2(xv.x * d, xv.y * d);
    }
    if (bid == 0 && t == 0) g_row[NN] = NE;
}

// Atomic-free counting-sort scatter: addr = row[dst] + slot[e]. 4 edges/thread.
// Block 0 also re-zeros g_part (scan is fully done by now).
__global__ void k_scatter(const void* __restrict__ edges) {
    __shared__ int sh_is64;
    if (threadIdx.x == 0) sh_is64 = detect_is64(edges);
    __syncthreads();
    if (blockIdx.x == 0 && threadIdx.x < NBLK1) g_part[threadIdx.x] = 0;

    int e0 = (blockIdx.x * blockDim.x + threadIdx.x) * 4;
    if (e0 >= NE) return;
    int s[4], d[4];
    if (sh_is64) {
        const longlong2* sp = (const longlong2*)edges;
        const longlong2* dp = (const longlong2*)((const long long*)edges + NE);
        longlong2 sa = sp[e0 >> 1], sb = sp[(e0 >> 1) + 1];
        longlong2 da = dp[e0 >> 1], db = dp[(e0 >> 1) + 1];
        s[0] = (int)sa.x; s[1] = (int)sa.y; s[2] = (int)sb.x; s[3] = (int)sb.y;
        d[0] = (int)da.x; d[1] = (int)da.y; d[2] = (int)db.x; d[3] = (int)db.y;
    } else {
        const int4* sp = (const int4*)edges;
        const int4* dp = (const int4*)((const int*)edges + NE);
        int4 sa = sp[e0 >> 2], da = dp[e0 >> 2];
        s[0] = sa.x; s[1] = sa.y; s[2] = sa.z; s[3] = sa.w;
        d[0] = da.x; d[1] = da.y; d[2] = da.z; d[3] = da.w;
    }
    ushort4 sl = *(const ushort4*)&g_slot[e0];
    g_sorted[__ldg(&g_row[d[0]]) + sl.x] = s[0];
    g_sorted[__ldg(&g_row[d[1]]) + sl.y] = s[1];
    g_sorted[__ldg(&g_row[d[2]]) + sl.z] = s[2];
    g_sorted[__ldg(&g_row[d[3]]) + sl.w] = s[3];
}

// Warp-per-node: layer-1 CSR gather of q + 2->64 GEMV + relu -> fp16 p row.
__global__ void __launch_bounds__(256) k_h1p(const float* __restrict__ W1,
                                             const float* __restrict__ b1) {
    int gt = blockIdx.x * blockDim.x + threadIdx.x;
    int n = gt >> 5;
    if (n >= NN) return;
    int lane = gt & 31;

    int e0 = g_row[n], e1 = g_row[n + 1];
    float ax = 0.f, ay = 0.f;
    for (int e = e0 + lane; e < e1; e += 32) {
        float2 q = __ldg(&g_q[g_sorted[e]]);
        ax += q.x; ay += q.y;
    }
    #pragma unroll
    for (int o = 16; o > 0; o >>= 1) {
        ax += __shfl_xor_sync(0xffffffffu, ax, o);
        ay += __shfl_xor_sync(0xffffffffu, ay, o);
    }
    float2 qn = g_q[n];
    float dv = g_dinv[n];
    float xax = (ax + qn.x) * dv;
    float xay = (ay + qn.y) * dv;

    int f = 2 * lane;
    float v0 = fmaf(xax, __ldg(&W1[f]),     fmaf(xay, __ldg(&W1[HID + f]),     __ldg(&b1[f])));
    float v1 = fmaf(xax, __ldg(&W1[f + 1]), fmaf(xay, __ldg(&W1[HID + f + 1]), __ldg(&b1[f + 1])));
    v0 = fmaxf(v0, 0.0f) * dv;
    v1 = fmaxf(v1, 0.0f) * dv;
    g_ph[n * 32 + lane] = __floats2half2_rn(v0, v1);
}

// Fused: fp16 CSR gather (layer-2 agg) + node-batched h2 GEMV + relu + pool
// + (last block) final FC output + state reset for next replay.
// 256 threads: fg = tid&7 (8 feats), rg = tid>>3; thread handles nodes rg*4+i.
__global__ void __launch_bounds__(256) k_gather2(
        const float* __restrict__ W2, const float* __restrict__ b2,
        const float* __restrict__ Wfc, const float* __restrict__ bfc,
        float* __restrict__ out) {
    __shared__ float  W2s[HID * HID];             // 16 KB, [k*64 + f]
    __shared__ __half hs[TILE2 * HS_STRIDE];      // 16.9 KB
    __shared__ int    sh_last;

    int tid = threadIdx.x;
    int fg = tid & 7, rg = tid >> 3;

    for (int i = tid; i < HID * HID; i += 256) W2s[i] = W2[i];
    float bloc[8];
    #pragma unroll
    for (int j = 0; j < 8; j++) bloc[j] = __ldg(&b2[8 * fg + j]);
    __syncthreads();

    float pool8[8] = {0.f, 0.f, 0.f, 0.f, 0.f, 0.f, 0.f, 0.f};
    const uint4* pt = (const uint4*)g_ph;

    for (int tile = blockIdx.x; tile < NT2; tile += gridDim.x) {
        // -------- stage A: gather agg for 4 nodes, write fp16 to hs --------
        #pragma unroll
        for (int i = 0; i < 4; i++) {
            int nl = rg * 4 + i;
            int n = tile * TILE2 + nl;
            float acc[8] = {0.f, 0.f, 0.f, 0.f, 0.f, 0.f, 0.f, 0.f};
            if (n < NN) {
                int e0 = g_row[n], e1 = g_row[n + 1];
                __half2 pa[4][4];
                #pragma unroll
                for (int j = 0; j < 4; j++)
                    #pragma unroll
                    for (int k = 0; k < 4; k++)
                        pa[j][k] = __floats2half2_rn(0.f, 0.f);
                int e = e0;
                // 8-deep MLP: batch 8 index loads, 8 row loads, then accumulate
                for (; e + 8 <= e1; e += 8) {
                    int sI[8];
                    uint4 r[8];
                    #pragma unroll
                    for (int u = 0; u < 8; u++) sI[u] = __ldg(&g_sorted[e + u]);
                    #pragma unroll
                    for (int u = 0; u < 8; u++) r[u] = __ldg(&pt[sI[u] * 8 + fg]);
                    #pragma unroll
                    for (int u = 0; u < 8; u++) {
                        pa[u & 3][0] = __hadd2(pa[u & 3][0], *(__half2*)&r[u].x);
                        pa[u & 3][1] = __hadd2(pa[u & 3][1], *(__half2*)&r[u].y);
                        pa[u & 3][2] = __hadd2(pa[u & 3][2], *(__half2*)&r[u].z);
                        pa[u & 3][3] = __hadd2(pa[u & 3][3], *(__half2*)&r[u].w);
                    }
                }
                for (; e + 4 <= e1; e += 4) {
                    #pragma unroll
                    for (int u = 0; u < 4; u++) {
                        int sv = __ldg(&g_sorted[e + u]);
                        uint4 r = __ldg(&pt[sv * 8 + fg]);
                        pa[u][0] = __hadd2(pa[u][0], *(__half2*)&r.x);
                        pa[u][1] = __hadd2(pa[u][1], *(__half2*)&r.y);
                        pa[u][2] = __hadd2(pa[u][2], *(__half2*)&r.z);
                        pa[u][3] = __hadd2(pa[u][3], *(__half2*)&r.w);
                    }
                }
                for (; e < e1; e++) {
                    int sv = __ldg(&g_sorted[e]);
                    uint4 r = __ldg(&pt[sv * 8 + fg]);
                    pa[0][0] = __hadd2(pa[0][0], *(__half2*)&r.x);
                    pa[0][1] = __hadd2(pa[0][1], *(__half2*)&r.y);
                    pa[0][2] = __hadd2(pa[0][2], *(__half2*)&r.z);
                    pa[0][3] = __hadd2(pa[0][3], *(__half2*)&r.w);
                }
                #pragma unroll
                for (int j = 0; j < 4; j++) {
                    #pragma unroll
                    for (int k = 0; k < 4; k++) {
                        float2 f2 = __half22float2(pa[j][k]);
                        acc[2 * k]     += f2.x;
                        acc[2 * k + 1] += f2.y;
                    }
                }
                // self loop in fp32
                uint4 rs = pt[n * 8 + fg];
                float2 s0 = __half22float2(*(__half2*)&rs.x);
                float2 s1 = __half22float2(*(__half2*)&rs.y);
                float2 s2 = __half22float2(*(__half2*)&rs.z);
                float2 s3 = __half22float2(*(__half2*)&rs.w);
                acc[0] += s0.x; acc[1] += s0.y; acc[2] += s1.x; acc[3] += s1.y;
                acc[4] += s2.x; acc[5] += s2.y; acc[6] += s3.x; acc[7] += s3.y;
                float sc = g_dinv[n];
                #pragma unroll
                for (int k = 0; k < 8; k++) acc[k] *= sc;
            }
            __half2* hw = (__half2*)&hs[nl * HS_STRIDE + 8 * fg];
            #pragma unroll
            for (int j = 0; j < 4; j++)
                hw[j] = __floats2half2_rn(acc[2 * j], acc[2 * j + 1]);
        }
        __syncthreads();

        // -------- stage B: h2 GEMV for 4 nodes, W2 amortized 4x,
        //          a-values loaded as half2 (k step 2) --------
        float o[4][8];
        #pragma unroll
        for (int i = 0; i < 4; i++)
            #pragma unroll
            for (int j = 0; j < 8; j++) o[i][j] = bloc[j];

        const __half* hp0 = &hs[(rg * 4 + 0) * HS_STRIDE];
        const __half* hp1 = &hs[(rg * 4 + 1) * HS_STRIDE];
        const __half* hp2 = &hs[(rg * 4 + 2) * HS_STRIDE];
        const __half* hp3 = &hs[(rg * 4 + 3) * HS_STRIDE];
        #pragma unroll 2
        for (int k2 = 0; k2 < HID / 2; k2++) {
            float2 a0p = __half22float2(*(const __half2*)&hp0[2 * k2]);
            float2 a1p = __half22float2(*(const __half2*)&hp1[2 * k2]);
            float2 a2p = __half22float2(*(const __half2*)&hp2[2 * k2]);
            float2 a3p = __half22float2(*(const __half2*)&hp3[2 * k2]);
            #pragma unroll
            for (int h = 0; h < 2; h++) {
                int k = 2 * k2 + h;
                float a0 = h ? a0p.y : a0p.x;
                float a1 = h ? a1p.y : a1p.x;
                float a2 = h ? a2p.y : a2p.x;
                float a3 = h ? a3p.y : a3p.x;
                float4 wA = *(const float4*)&W2s[k * HID + 8 * fg];
                float4 wB = *(const float4*)&W2s[k * HID + 8 * fg + 4];
                o[0][0] = fmaf(a0, wA.x, o[0][0]); o[0][1] = fmaf(a0, wA.y, o[0][1]);
                o[0][2] = fmaf(a0, wA.z, o[0][2]); o[0][3] = fmaf(a0, wA.w, o[0][3]);
                o[0][4] = fmaf(a0, wB.x, o[0][4]); o[0][5] = fmaf(a0, wB.y, o[0][5]);
                o[0][6] = fmaf(a0, wB.z, o[0][6]); o[0][7] = fmaf(a0, wB.w, o[0][7]);
                o[1][0] = fmaf(a1, wA.x, o[1][0]); o[1][1] = fmaf(a1, wA.y, o[1][1]);
                o[1][2] = fmaf(a1, wA.z, o[1][2]); o[1][3] = fmaf(a1, wA.w, o[1][3]);
                o[1][4] = fmaf(a1, wB.x, o[1][4]); o[1][5] = fmaf(a1, wB.y, o[1][5]);
                o[1][6] = fmaf(a1, wB.z, o[1][6]); o[1][7] = fmaf(a1, wB.w, o[1][7]);
                o[2][0] = fmaf(a2, wA.x, o[2][0]); o[2][1] = fmaf(a2, wA.y, o[2][1]);
                o[2][2] = fmaf(a2, wA.z, o[2][2]); o[2][3] = fmaf(a2, wA.w, o[2][3]);
                o[2][4] = fmaf(a2, wB.x, o[2][4]); o[2][5] = fmaf(a2, wB.y, o[2][5]);
                o[2][6] = fmaf(a2, wB.z, o[2][6]); o[2][7] = fmaf(a2, wB.w, o[2][7]);
                o[3][0] = fmaf(a3, wA.x, o[3][0]); o[3][1] = fmaf(a3, wA.y, o[3][1]);
                o[3][2] = fmaf(a3, wA.z, o[3][2]); o[3][3] = fmaf(a3, wA.w, o[3][3]);
                o[3][4] = fmaf(a3, wB.x, o[3][4]); o[3][5] = fmaf(a3, wB.y, o[3][5]);
                o[3][6] = fmaf(a3, wB.z, o[3][6]); o[3][7] = fmaf(a3, wB.w, o[3][7]);
            }
        }
        #pragma unroll
        for (int i = 0; i < 4; i++) {
            int n = tile * TILE2 + rg * 4 + i;
            if (n < NN) {
                #pragma unroll
                for (int j = 0; j < 8; j++)
                    pool8[j] += fmaxf(o[i][j], 0.f);
            }
        }
        __syncthreads();   // hs reused next tile
    }

    // -------- final pool reduction (reuse hs as float scratch) --------
    float* hsf = (float*)hs;   // 32*64 floats = 8 KB
    #pragma unroll
    for (int j = 0; j < 8; j++)
        hsf[rg * HID + 8 * fg + j] = pool8[j];
    __syncthreads();
    if (tid < HID) {
        float s = 0.f;
        #pragma unroll 8
        for (int r = 0; r < 32; r++) s += hsf[r * HID + tid];
        atomicAdd(&g_pool[tid], s);
    }

    // -------- last block: final FC output + state reset for next replay ----
    if (tid == 0) {
        __threadfence();
        int t = atomicAdd(&g_done, 1);
        sh_last = (t == gridDim.x - 1);
    }
    __syncthreads();
    if (sh_last) {
        float s = 0.f;
        if (tid < 32) {
            s = g_pool[tid] * __ldg(&Wfc[tid]) + g_pool[tid + 32] * __ldg(&Wfc[tid + 32]);
            #pragma unroll
            for (int o2 = 16; o2 > 0; o2 >>= 1) s += __shfl_down_sync(0xffffffffu, s, o2);
        }
        __syncthreads();               // all reads of g_pool done
        if (tid < HID) g_pool[tid] = 0.f;
        if (tid == 0) {
            g_done = 0;
            out[0] = s * (1.0f / NN) + __ldg(&bfc[0]);
        }
    }
}

// ---------------- launch ----------------
extern "C" void kernel_launch(void* const* d_in, const int* in_sizes, int n_in,
                              void* d_out, int out_size) {
    const float2* x2    = (const float2*)d_in[0];
    const void*   edges = d_in[1];
    const float*  W1    = (const float*)d_in[2];
    const float*  b1    = (const float*)d_in[3];
    const float*  W2    = (const float*)d_in[4];
    const float*  b2    = (const float*)d_in[5];
    const float*  Wfc   = (const float*)d_in[6];
    const float*  bfc   = (const float*)d_in[7];
    float* out = (float*)d_out;

    const int T = 256;
    k_count<<<(NE / 4 + T - 1) / T, T>>>(edges);
    k_scan<<<NBLK1, SCAN_B>>>(x2);
    k_scatter<<<(NE / 4 + T - 1) / T, T>>>(edges);
    k_h1p<<<(NN * 32 + T - 1) / T, T>>>(W1, b1);
    k_gather2<<<NT2, T>>>(W2, b2, Wfc, bfc, out);
}

// round 14
// speedup vs baseline: 1.0838x; 1.0317x over previous
#include <cuda_runtime.h>
#include <cuda_fp16.h>
#include <cstdint>

#define NN 100000
#define NE 3200000
#define HID 64
#define SCAN_B 512
#define NBLK1 ((NN + SCAN_B - 1) / SCAN_B)   // 196
#define TILE2 128
#define NT2 ((NN + TILE2 - 1) / TILE2)       // 782
#define HS_STRIDE 66                          // halves; conflict-free staging
#define ST_AGG  (1 << 28)
#define ST_PRE  (2 << 28)
#define VMASK   0x0FFFFFFF

// ---------------- scratch (device globals; zero-initialized at load) -------
// Pipeline is self-cleaning across graph replays (g_cnt by k_scan, g_part by
// k_scatter, g_pool/g_done by k_gather2's last block).
__device__ int            g_cnt[NN];
__device__ float          g_dinv[NN];
__device__ float2         g_q[NN];         // q = dinv * x (layer-1 gather table)
__device__ int            g_row[NN + 1];   // CSR row pointers (by dst)
__device__ unsigned short g_slot[NE];      // within-bucket slot per edge
__device__ int            g_sorted[NE];    // src ids sorted by dst
__device__ __half2        g_ph[NN * 32];   // p = dinv*relu(h1), fp16, 128 B/node
__device__ float          g_pool[HID];
__device__ int            g_part[NBLK1];   // lookback: status<<28 | value
__device__ int            g_done;

// Detect int64 vs int32 storage from the first 8 qwords.
__device__ __forceinline__ int detect_is64(const void* edges) {
    const unsigned long long* e64 = (const unsigned long long*)edges;
    int is64 = 1;
    #pragma unroll
    for (int k = 0; k < 8; k++)
        if (e64[k] >= (unsigned long long)NN) { is64 = 0; break; }
    return is64;
}

// ---------------- kernels ----------------

// Histogram dst AND record each edge's slot (ushort). 4 edges/thread.
__global__ void k_count(const void* __restrict__ edges) {
    __shared__ int sh_is64;
    if (threadIdx.x == 0) sh_is64 = detect_is64(edges);
    __syncthreads();
    int e0 = (blockIdx.x * blockDim.x + threadIdx.x) * 4;
    if (e0 >= NE) return;
    int d[4];
    if (sh_is64) {
        const longlong2* d2 = (const longlong2*)((const long long*)edges + NE);
        longlong2 a = d2[e0 >> 1], b = d2[(e0 >> 1) + 1];
        d[0] = (int)a.x; d[1] = (int)a.y; d[2] = (int)b.x; d[3] = (int)b.y;
    } else {
        const int4* d4 = (const int4*)((const int*)edges + NE);
        int4 a = d4[e0 >> 2];
        d[0] = a.x; d[1] = a.y; d[2] = a.z; d[3] = a.w;
    }
    ushort4 sl;
    sl.x = (unsigned short)atomicAdd(&g_cnt[d[0]], 1);
    sl.y = (unsigned short)atomicAdd(&g_cnt[d[1]], 1);
    sl.z = (unsigned short)atomicAdd(&g_cnt[d[2]], 1);
    sl.w = (unsigned short)atomicAdd(&g_cnt[d[3]], 1);
    *(ushort4*)&g_slot[e0] = sl;
}

// Single-kernel exclusive scan (decoupled lookback) + dinv + q tables.
// Also re-zeros g_cnt for the next graph replay.
__global__ void __launch_bounds__(SCAN_B) k_scan(const float2* __restrict__ x2) {
    __shared__ int wsum[SCAN_B / 32];
    __shared__ int sh_total, sh_base;
    int bid = blockIdx.x, t = threadIdx.x;
    int i = bid * SCAN_B + t;
    int lane = t & 31, w = t >> 5;

    int v = (i < NN) ? g_cnt[i] : 0;
    int s = v;
    #pragma unroll
    for (int o = 1; o < 32; o <<= 1) {
        int u = __shfl_up_sync(0xffffffffu, s, o);
        if (lane >= o) s += u;
    }
    if (lane == 31) wsum[w] = s;
    __syncthreads();
    if (w == 0) {
        int ws = (lane < SCAN_B / 32) ? wsum[lane] : 0;
        #pragma unroll
        for (int o = 1; o < 16; o <<= 1) {
            int u = __shfl_up_sync(0xffffffffu, ws, o);
            if (lane >= o) ws += u;
        }
        if (lane < SCAN_B / 32) wsum[lane] = ws;
    }
    __syncthreads();
    int base_l = (w > 0) ? wsum[w - 1] : 0;
    int incl = s + base_l;                 // inclusive within block
    if (t == SCAN_B - 1) sh_total = incl;
    __syncthreads();
    int total = sh_total;

    if (t == 0) {
        int pk = (bid == 0) ? (ST_PRE | total) : (ST_AGG | total);
        *(volatile int*)&g_part[bid] = pk;
        __threadfence();
    }

    if (bid == 0) {
        if (t == 0) sh_base = 0;
    } else if (w == 0) {
        int run = 0, lag = 1;
        for (;;) {
            int idx = bid - lag - lane;
            int pv = (idx >= 0) ? *(volatile int*)&g_part[idx] : ST_PRE;
            if (!__all_sync(0xffffffffu, (pv & ~VMASK) != 0)) continue;
            unsigned pm = __ballot_sync(0xffffffffu, (pv & ~VMASK) == ST_PRE);
            int val = pv & VMASK;
            if (pm) {
                int pl = __ffs(pm) - 1;
                int c = (lane <= pl) ? val : 0;
                #pragma unroll
                for (int o = 16; o > 0; o >>= 1) c += __shfl_xor_sync(0xffffffffu, c, o);
                run += c;
                break;
            } else {
                int c = val;
                #pragma unroll
                for (int o = 16; o > 0; o >>= 1) c += __shfl_xor_sync(0xffffffffu, c, o);
                run += c;
                lag += 32;
            }
        }
        if (lane == 0) {
            *(volatile int*)&g_part[bid] = ST_PRE | ((run + total) & VMASK);
            __threadfence();
            sh_base = run;
        }
    }
    __syncthreads();
    int base_g = sh_base;

    if (i < NN) {
        g_row[i] = base_g + incl - v;      // exclusive global prefix
        g_cnt[i] = 0;                      // self-clean for next replay
        float d = rsqrtf((float)v + 1.0f);
        g_dinv[i] = d;
        float2 xv = x2[i];
        g_q[i] = make_float2(xv.x * d, xv.y * d);
    }
    if (bid == 0 && t == 0) g_row[NN] = NE;
}

// Atomic-free counting-sort scatter: addr = row[dst] + slot[e]. 4 edges/thread.
// Block 0 also re-zeros g_part (scan is fully done by now).
__global__ void k_scatter(const void* __restrict__ edges) {
    __shared__ int sh_is64;
    if (threadIdx.x == 0) sh_is64 = detect_is64(edges);
    __syncthreads();
    if (blockIdx.x == 0 && threadIdx.x < NBLK1) g_part[threadIdx.x] = 0;

    int e0 = (blockIdx.x * blockDim.x + threadIdx.x) * 4;
    if (e0 >= NE) return;
    int s[4], d[4];
    if (sh_is64) {
        const longlong2* sp = (const longlong2*)edges;
        const longlong2* dp = (const longlong2*)((const long long*)edges + NE);
        longlong2 sa = sp[e0 >> 1], sb = sp[(e0 >> 1) + 1];
        longlong2 da = dp[e0 >> 1], db = dp[(e0 >> 1) + 1];
        s[0] = (int)sa.x; s[1] = (int)sa.y; s[2] = (int)sb.x; s[3] = (int)sb.y;
        d[0] = (int)da.x; d[1] = (int)da.y; d[2] = (int)db.x; d[3] = (int)db.y;
    } else {
        const int4* sp = (const int4*)edges;
        const int4* dp = (const int4*)((const int*)edges + NE);
        int4 sa = sp[e0 >> 2], da = dp[e0 >> 2];
        s[0] = sa.x; s[1] = sa.y; s[2] = sa.z; s[3] = sa.w;
        d[0] = da.x; d[1] = da.y; d[2] = da.z; d[3] = da.w;
    }
    ushort4 sl = *(const ushort4*)&g_slot[e0];
    g_sorted[__ldg(&g_row[d[0]]) + sl.x] = s[0];
    g_sorted[__ldg(&g_row[d[1]]) + sl.y] = s[1];
    g_sorted[__ldg(&g_row[d[2]]) + sl.z] = s[2];
    g_sorted[__ldg(&g_row[d[3]]) + sl.w] = s[3];
}

// Thread-per-node: layer-1 CSR gather (8-deep MLP, no shuffles) +
// 2->64 GEMV from smem weights + relu -> fp16 p row (8x uint4 stores).
__global__ void __launch_bounds__(256) k_h1p(const float* __restrict__ W1,
                                             const float* __restrict__ b1) {
    __shared__ float W1s[2 * HID];
    __shared__ float b1s[HID];
    int tid = threadIdx.x;
    if (tid < 2 * HID) W1s[tid] = W1[tid];
    if (tid < HID) b1s[tid] = b1[tid];
    __syncthreads();

    int n = blockIdx.x * blockDim.x + tid;
    if (n >= NN) return;

    int e0 = g_row[n], e1 = g_row[n + 1];
    float ax = 0.f, ay = 0.f;
    int e = e0;
    for (; e + 8 <= e1; e += 8) {
        int sI[8];
        #pragma unroll
        for (int u = 0; u < 8; u++) sI[u] = __ldg(&g_sorted[e + u]);
        float2 qv[8];
        #pragma unroll
        for (int u = 0; u < 8; u++) qv[u] = __ldg(&g_q[sI[u]]);
        #pragma unroll
        for (int u = 0; u < 8; u++) { ax += qv[u].x; ay += qv[u].y; }
    }
    for (; e < e1; e++) {
        float2 qv = __ldg(&g_q[__ldg(&g_sorted[e])]);
        ax += qv.x; ay += qv.y;
    }
    float2 qn = g_q[n];
    float dv = g_dinv[n];
    float xax = (ax + qn.x) * dv;
    float xay = (ay + qn.y) * dv;

    uint4* dst = (uint4*)&g_ph[n * 32];
    #pragma unroll
    for (int c = 0; c < 8; c++) {
        unsigned hh[4];
        #pragma unroll
        for (int j = 0; j < 4; j++) {
            int f = c * 8 + 2 * j;
            float v0 = fmaf(xax, W1s[f],     fmaf(xay, W1s[HID + f],     b1s[f]));
            float v1 = fmaf(xax, W1s[f + 1], fmaf(xay, W1s[HID + f + 1], b1s[f + 1]));
            v0 = fmaxf(v0, 0.0f) * dv;
            v1 = fmaxf(v1, 0.0f) * dv;
            __half2 h2v = __floats2half2_rn(v0, v1);
            hh[j] = *(unsigned*)&h2v;
        }
        uint4 u4;
        u4.x = hh[0]; u4.y = hh[1]; u4.z = hh[2]; u4.w = hh[3];
        dst[c] = u4;
    }
}

// Fused: fp16 CSR gather (layer-2 agg) + node-batched h2 GEMV + relu + pool
// + (last block) final FC output + state reset for next replay.
// 256 threads: fg = tid&7 (8 feats), rg = tid>>3; thread handles nodes rg*4+i.
__global__ void __launch_bounds__(256) k_gather2(
        const float* __restrict__ W2, const float* __restrict__ b2,
        const float* __restrict__ Wfc, const float* __restrict__ bfc,
        float* __restrict__ out) {
    __shared__ float  W2s[HID * HID];             // 16 KB, [k*64 + f]
    __shared__ __half hs[TILE2 * HS_STRIDE];      // 16.9 KB
    __shared__ int    sh_last;

    int tid = threadIdx.x;
    int fg = tid & 7, rg = tid >> 3;

    for (int i = tid; i < HID * HID; i += 256) W2s[i] = W2[i];
    float bloc[8];
    #pragma unroll
    for (int j = 0; j < 8; j++) bloc[j] = __ldg(&b2[8 * fg + j]);
    __syncthreads();

    float pool8[8] = {0.f, 0.f, 0.f, 0.f, 0.f, 0.f, 0.f, 0.f};
    const uint4* pt = (const uint4*)g_ph;

    for (int tile = blockIdx.x; tile < NT2; tile += gridDim.x) {
        // -------- stage A: gather agg for 4 nodes, write fp16 to hs --------
        #pragma unroll
        for (int i = 0; i < 4; i++) {
            int nl = rg * 4 + i;
            int n = tile * TILE2 + nl;
            float acc[8] = {0.f, 0.f, 0.f, 0.f, 0.f, 0.f, 0.f, 0.f};
            if (n < NN) {
                int e0 = g_row[n], e1 = g_row[n + 1];
                __half2 pa[4][4];
                #pragma unroll
                for (int j = 0; j < 4; j++)
                    #pragma unroll
                    for (int k = 0; k < 4; k++)
                        pa[j][k] = __floats2half2_rn(0.f, 0.f);
                int e = e0;
                // 8-deep MLP: batch 8 index loads, 8 row loads, then accumulate
                for (; e + 8 <= e1; e += 8) {
                    int sI[8];
                    uint4 r[8];
                    #pragma unroll
                    for (int u = 0; u < 8; u++) sI[u] = __ldg(&g_sorted[e + u]);
                    #pragma unroll
                    for (int u = 0; u < 8; u++) r[u] = __ldg(&pt[sI[u] * 8 + fg]);
                    #pragma unroll
                    for (int u = 0; u < 8; u++) {
                        pa[u & 3][0] = __hadd2(pa[u & 3][0], *(__half2*)&r[u].x);
                        pa[u & 3][1] = __hadd2(pa[u & 3][1], *(__half2*)&r[u].y);
                        pa[u & 3][2] = __hadd2(pa[u & 3][2], *(__half2*)&r[u].z);
                        pa[u & 3][3] = __hadd2(pa[u & 3][3], *(__half2*)&r[u].w);
                    }
                }
                for (; e + 4 <= e1; e += 4) {
                    #pragma unroll
                    for (int u = 0; u < 4; u++) {
                        int sv = __ldg(&g_sorted[e + u]);
                        uint4 r = __ldg(&pt[sv * 8 + fg]);
                        pa[u][0] = __hadd2(pa[u][0], *(__half2*)&r.x);
                        pa[u][1] = __hadd2(pa[u][1], *(__half2*)&r.y);
                        pa[u][2] = __hadd2(pa[u][2], *(__half2*)&r.z);
                        pa[u][3] = __hadd2(pa[u][3], *(__half2*)&r.w);
                    }
                }
                for (; e < e1; e++) {
                    int sv = __ldg(&g_sorted[e]);
                    uint4 r = __ldg(&pt[sv * 8 + fg]);
                    pa[0][0] = __hadd2(pa[0][0], *(__half2*)&r.x);
                    pa[0][1] = __hadd2(pa[0][1], *(__half2*)&r.y);
                    pa[0][2] = __hadd2(pa[0][2], *(__half2*)&r.z);
                    pa[0][3] = __hadd2(pa[0][3], *(__half2*)&r.w);
                }
                #pragma unroll
                for (int j = 0; j < 4; j++) {
                    #pragma unroll
                    for (int k = 0; k < 4; k++) {
                        float2 f2 = __half22float2(pa[j][k]);
                        acc[2 * k]     += f2.x;
                        acc[2 * k + 1] += f2.y;
                    }
                }
                // self loop in fp32
                uint4 rs = pt[n * 8 + fg];
                float2 s0 = __half22float2(*(__half2*)&rs.x);
                float2 s1 = __half22float2(*(__half2*)&rs.y);
                float2 s2 = __half22float2(*(__half2*)&rs.z);
                float2 s3 = __half22float2(*(__half2*)&rs.w);
                acc[0] += s0.x; acc[1] += s0.y; acc[2] += s1.x; acc[3] += s1.y;
                acc[4] += s2.x; acc[5] += s2.y; acc[6] += s3.x; acc[7] += s3.y;
                float sc = g_dinv[n];
                #pragma unroll
                for (int k = 0; k < 8; k++) acc[k] *= sc;
            }
            __half2* hw = (__half2*)&hs[nl * HS_STRIDE + 8 * fg];
            #pragma unroll
            for (int j = 0; j < 4; j++)
                hw[j] = __floats2half2_rn(acc[2 * j], acc[2 * j + 1]);
        }
        __syncthreads();

        // -------- stage B: h2 GEMV for 4 nodes, W2 amortized 4x,
        //          a-values loaded as half2 (k step 2) --------
        float o[4][8];
        #pragma unroll
        for (int i = 0; i < 4; i++)
            #pragma unroll
            for (int j = 0; j < 8; j++) o[i][j] = bloc[j];

        const __half* hp0 = &hs[(rg * 4 + 0) * HS_STRIDE];
        const __half* hp1 = &hs[(rg * 4 + 1) * HS_STRIDE];
        const __half* hp2 = &hs[(rg * 4 + 2) * HS_STRIDE];
        const __half* hp3 = &hs[(rg * 4 + 3) * HS_STRIDE];
        #pragma unroll 2
        for (int k2 = 0; k2 < HID / 2; k2++) {
            float2 a0p = __half22float2(*(const __half2*)&hp0[2 * k2]);
            float2 a1p = __half22float2(*(const __half2*)&hp1[2 * k2]);
            float2 a2p = __half22float2(*(const __half2*)&hp2[2 * k2]);
            float2 a3p = __half22float2(*(const __half2*)&hp3[2 * k2]);
            #pragma unroll
            for (int h = 0; h < 2; h++) {
                int k = 2 * k2 + h;
                float a0 = h ? a0p.y : a0p.x;
                float a1 = h ? a1p.y : a1p.x;
                float a2 = h ? a2p.y : a2p.x;
                float a3 = h ? a3p.y : a3p.x;
                float4 wA = *(const float4*)&W2s[k * HID + 8 * fg];
                float4 wB = *(const float4*)&W2s[k * HID + 8 * fg + 4];
                o[0][0] = fmaf(a0, wA.x, o[0][0]); o[0][1] = fmaf(a0, wA.y, o[0][1]);
                o[0][2] = fmaf(a0, wA.z, o[0][2]); o[0][3] = fmaf(a0, wA.w, o[0][3]);
                o[0][4] = fmaf(a0, wB.x, o[0][4]); o[0][5] = fmaf(a0, wB.y, o[0][5]);
                o[0][6] = fmaf(a0, wB.z, o[0][6]); o[0][7] = fmaf(a0, wB.w, o[0][7]);
                o[1][0] = fmaf(a1, wA.x, o[1][0]); o[1][1] = fmaf(a1, wA.y, o[1][1]);
                o[1][2] = fmaf(a1, wA.z, o[1][2]); o[1][3] = fmaf(a1, wA.w, o[1][3]);
                o[1][4] = fmaf(a1, wB.x, o[1][4]); o[1][5] = fmaf(a1, wB.y, o[1][5]);
                o[1][6] = fmaf(a1, wB.z, o[1][6]); o[1][7] = fmaf(a1, wB.w, o[1][7]);
                o[2][0] = fmaf(a2, wA.x, o[2][0]); o[2][1] = fmaf(a2, wA.y, o[2][1]);
                o[2][2] = fmaf(a2, wA.z, o[2][2]); o[2][3] = fmaf(a2, wA.w, o[2][3]);
                o[2][4] = fmaf(a2, wB.x, o[2][4]); o[2][5] = fmaf(a2, wB.y, o[2][5]);
                o[2][6] = fmaf(a2, wB.z, o[2][6]); o[2][7] = fmaf(a2, wB.w, o[2][7]);
                o[3][0] = fmaf(a3, wA.x, o[3][0]); o[3][1] = fmaf(a3, wA.y, o[3][1]);
                o[3][2] = fmaf(a3, wA.z, o[3][2]); o[3][3] = fmaf(a3, wA.w, o[3][3]);
                o[3][4] = fmaf(a3, wB.x, o[3][4]); o[3][5] = fmaf(a3, wB.y, o[3][5]);
                o[3][6] = fmaf(a3, wB.z, o[3][6]); o[3][7] = fmaf(a3, wB.w, o[3][7]);
            }
        }
        #pragma unroll
        for (int i = 0; i < 4; i++) {
            int n = tile * TILE2 + rg * 4 + i;
            if (n < NN) {
                #pragma unroll
                for (int j = 0; j < 8; j++)
                    pool8[j] += fmaxf(o[i][j], 0.f);
            }
        }
        __syncthreads();   // hs reused next tile
    }

    // -------- final pool reduction (reuse hs as float scratch) --------
    float* hsf = (float*)hs;   // 32*64 floats = 8 KB
    #pragma unroll
    for (int j = 0; j < 8; j++)
        hsf[rg * HID + 8 * fg + j] = pool8[j];
    __syncthreads();
    if (tid < HID) {
        float s = 0.f;
        #pragma unroll 8
        for (int r = 0; r < 32; r++) s += hsf[r * HID + tid];
        atomicAdd(&g_pool[tid], s);
    }

    // -------- last block: final FC output + state reset for next replay ----
    if (tid == 0) {
        __threadfence();
        int t = atomicAdd(&g_done, 1);
        sh_last = (t == gridDim.x - 1);
    }
    __syncthreads();
    if (sh_last) {
        float s = 0.f;
        if (tid < 32) {
            s = g_pool[tid] * __ldg(&Wfc[tid]) + g_pool[tid + 32] * __ldg(&Wfc[tid + 32]);
            #pragma unroll
            for (int o2 = 16; o2 > 0; o2 >>= 1) s += __shfl_down_sync(0xffffffffu, s, o2);
        }
        __syncthreads();               // all reads of g_pool done
        if (tid < HID) g_pool[tid] = 0.f;
        if (tid == 0) {
            g_done = 0;
            out[0] = s * (1.0f / NN) + __ldg(&bfc[0]);
        }
    }
}

// ---------------- launch ----------------
extern "C" void kernel_launch(void* const* d_in, const int* in_sizes, int n_in,
                              void* d_out, int out_size) {
    const float2* x2    = (const float2*)d_in[0];
    const void*   edges = d_in[1];
    const float*  W1    = (const float*)d_in[2];
    const float*  b1    = (const float*)d_in[3];
    const float*  W2    = (const float*)d_in[4];
    const float*  b2    = (const float*)d_in[5];
    const float*  Wfc   = (const float*)d_in[6];
    const float*  bfc   = (const float*)d_in[7];
    float* out = (float*)d_out;

    const int T = 256;
    k_count<<<(NE / 4 + T - 1) / T, T>>>(edges);
    k_scan<<<NBLK1, SCAN_B>>>(x2);
    k_scatter<<<(NE / 4 + T - 1) / T, T>>>(edges);
    k_h1p<<<(NN + T - 1) / T, T>>>(W1, b1);
    k_gather2<<<NT2, T>>>(W2, b2, Wfc, bfc, out);
}

// round 15
// speedup vs baseline: 1.0898x; 1.0055x over previous
#include <cuda_runtime.h>
#include <cuda_fp16.h>
#include <cstdint>

#define NN 100000
#define NE 3200000
#define HID 64
#define SCAN_B 512
#define NBLK1 ((NN + SCAN_B - 1) / SCAN_B)   // 196
#define TILE2 128
#define NT2 ((NN + TILE2 - 1) / TILE2)       // 782
#define HS_STRIDE 66                          // halves; conflict-free staging
#define ST_AGG  (1 << 28)
#define ST_PRE  (2 << 28)
#define VMASK   0x0FFFFFFF

// ---------------- scratch (device globals; zero-initialized at load) -------
// Pipeline is self-cleaning across graph replays (g_cnt by k_scan, g_part by
// k_scatter, g_pool/g_done by k_gather2's last block).
__device__ int            g_cnt[NN];
__device__ float          g_dinv[NN];
__device__ float2         g_q[NN];         // q = dinv * x (layer-1 gather table)
__device__ int            g_row[NN + 1];   // CSR row pointers (by dst)
__device__ unsigned short g_slot[NE];      // within-bucket slot per edge
__device__ int            g_sorted[NE];    // src ids sorted by dst
__device__ __half2        g_ph[NN * 32];   // p = dinv*relu(h1), fp16, 128 B/node
__device__ float          g_pool[HID];
__device__ int            g_part[NBLK1];   // lookback: status<<28 | value
__device__ int            g_done;

// Detect int64 vs int32 storage from the first 8 qwords.
__device__ __forceinline__ int detect_is64(const void* edges) {
    const unsigned long long* e64 = (const unsigned long long*)edges;
    int is64 = 1;
    #pragma unroll
    for (int k = 0; k < 8; k++)
        if (e64[k] >= (unsigned long long)NN) { is64 = 0; break; }
    return is64;
}

// ---------------- kernels ----------------

// Histogram dst AND record each edge's slot (ushort). 4 edges/thread.
__global__ void k_count(const void* __restrict__ edges) {
    __shared__ int sh_is64;
    if (threadIdx.x == 0) sh_is64 = detect_is64(edges);
    __syncthreads();
    int e0 = (blockIdx.x * blockDim.x + threadIdx.x) * 4;
    if (e0 >= NE) return;
    int d[4];
    if (sh_is64) {
        const longlong2* d2 = (const longlong2*)((const long long*)edges + NE);
        longlong2 a = d2[e0 >> 1], b = d2[(e0 >> 1) + 1];
        d[0] = (int)a.x; d[1] = (int)a.y; d[2] = (int)b.x; d[3] = (int)b.y;
    } else {
        const int4* d4 = (const int4*)((const int*)edges + NE);
        int4 a = d4[e0 >> 2];
        d[0] = a.x; d[1] = a.y; d[2] = a.z; d[3] = a.w;
    }
    ushort4 sl;
    sl.x = (unsigned short)atomicAdd(&g_cnt[d[0]], 1);
    sl.y = (unsigned short)atomicAdd(&g_cnt[d[1]], 1);
    sl.z = (unsigned short)atomicAdd(&g_cnt[d[2]], 1);
    sl.w = (unsigned short)atomicAdd(&g_cnt[d[3]], 1);
    *(ushort4*)&g_slot[e0] = sl;
}

// Single-kernel exclusive scan (decoupled lookback) + dinv + q tables.
// Also re-zeros g_cnt for the next graph replay.
__global__ void __launch_bounds__(SCAN_B) k_scan(const float2* __restrict__ x2) {
    __shared__ int wsum[SCAN_B / 32];
    __shared__ int sh_total, sh_base;
    int bid = blockIdx.x, t = threadIdx.x;
    int i = bid * SCAN_B + t;
    int lane = t & 31, w = t >> 5;

    int v = (i < NN) ? g_cnt[i] : 0;
    int s = v;
    #pragma unroll
    for (int o = 1; o < 32; o <<= 1) {
        int u = __shfl_up_sync(0xffffffffu, s, o);
        if (lane >= o) s += u;
    }
    if (lane == 31) wsum[w] = s;
    __syncthreads();
    if (w == 0) {
        int ws = (lane < SCAN_B / 32) ? wsum[lane] : 0;
        #pragma unroll
        for (int o = 1; o < 16; o <<= 1) {
            int u = __shfl_up_sync(0xffffffffu, ws, o);
            if (lane >= o) ws += u;
        }
        if (lane < SCAN_B / 32) wsum[lane] = ws;
    }
    __syncthreads();
    int base_l = (w > 0) ? wsum[w - 1] : 0;
    int incl = s + base_l;                 // inclusive within block
    if (t == SCAN_B - 1) sh_total = incl;
    __syncthreads();
    int total = sh_total;

    if (t == 0) {
        int pk = (bid == 0) ? (ST_PRE | total) : (ST_AGG | total);
        *(volatile int*)&g_part[bid] = pk;
        __threadfence();
    }

    if (bid == 0) {
        if (t == 0) sh_base = 0;
    } else if (w == 0) {
        int run = 0, lag = 1;
        for (;;) {
            int idx = bid - lag - lane;
            int pv = (idx >= 0) ? *(volatile int*)&g_part[idx] : ST_PRE;
            if (!__all_sync(0xffffffffu, (pv & ~VMASK) != 0)) continue;
            unsigned pm = __ballot_sync(0xffffffffu, (pv & ~VMASK) == ST_PRE);
            int val = pv & VMASK;
            if (pm) {
                int pl = __ffs(pm) - 1;
                int c = (lane <= pl) ? val : 0;
                #pragma unroll
                for (int o = 16; o > 0; o >>= 1) c += __shfl_xor_sync(0xffffffffu, c, o);
                run += c;
                break;
            } else {
                int c = val;
                #pragma unroll
                for (int o = 16; o > 0; o >>= 1) c += __shfl_xor_sync(0xffffffffu, c, o);
                run += c;
                lag += 32;
            }
        }
        if (lane == 0) {
            *(volatile int*)&g_part[bid] = ST_PRE | ((run + total) & VMASK);
            __threadfence();
            sh_base = run;
        }
    }
    __syncthreads();
    int base_g = sh_base;

    if (i < NN) {
        g_row[i] = base_g + incl - v;      // exclusive global prefix
        g_cnt[i] = 0;                      // self-clean for next replay
        float d = rsqrtf((float)v + 1.0f);
        g_dinv[i] = d;
        float2 xv = x2[i];
        g_q[i] = make_float2(xv.x * d, xv.y * d);
    }
    if (bid == 0 && t == 0) g_row[NN] = NE;
}

// Atomic-free counting-sort scatter: addr = row[dst] + slot[e]. 4 edges/thread.
// Block 0 also re-zeros g_part (scan is fully done by now).
__global__ void k_scatter(const void* __restrict__ edges) {
    __shared__ int sh_is64;
    if (threadIdx.x == 0) sh_is64 = detect_is64(edges);
    __syncthreads();
    if (blockIdx.x == 0 && threadIdx.x < NBLK1) g_part[threadIdx.x] = 0;

    int e0 = (blockIdx.x * blockDim.x + threadIdx.x) * 4;
    if (e0 >= NE) return;
    int s[4], d[4];
    if (sh_is64) {
        const longlong2* sp = (const longlong2*)edges;
        const longlong2* dp = (const longlong2*)((const long long*)edges + NE);
        longlong2 sa = sp[e0 >> 1], sb = sp[(e0 >> 1) + 1];
        longlong2 da = dp[e0 >> 1], db = dp[(e0 >> 1) + 1];
        s[0] = (int)sa.x; s[1] = (int)sa.y; s[2] = (int)sb.x; s[3] = (int)sb.y;
        d[0] = (int)da.x; d[1] = (int)da.y; d[2] = (int)db.x; d[3] = (int)db.y;
    } else {
        const int4* sp = (const int4*)edges;
        const int4* dp = (const int4*)((const int*)edges + NE);
        int4 sa = sp[e0 >> 2], da = dp[e0 >> 2];
        s[0] = sa.x; s[1] = sa.y; s[2] = sa.z; s[3] = sa.w;
        d[0] = da.x; d[1] = da.y; d[2] = da.z; d[3] = da.w;
    }
    ushort4 sl = *(const ushort4*)&g_slot[e0];
    g_sorted[__ldg(&g_row[d[0]]) + sl.x] = s[0];
    g_sorted[__ldg(&g_row[d[1]]) + sl.y] = s[1];
    g_sorted[__ldg(&g_row[d[2]]) + sl.z] = s[2];
    g_sorted[__ldg(&g_row[d[3]]) + sl.w] = s[3];
}

// Two threads per node: each sums alternate edges (8-deep batching), one
// shfl_xor pair combines, each thread emits 32 of the 64 fp16 features.
__global__ void __launch_bounds__(256) k_h1p(const float* __restrict__ W1,
                                             const float* __restrict__ b1) {
    __shared__ float W1s[2 * HID];
    __shared__ float b1s[HID];
    int tid = threadIdx.x;
    if (tid < 2 * HID) W1s[tid] = W1[tid];
    if (tid < HID) b1s[tid] = b1[tid];
    __syncthreads();

    int gt = blockIdx.x * blockDim.x + tid;
    int n = gt >> 1;
    if (n >= NN) return;
    int half = gt & 1;

    int e0 = g_row[n], e1 = g_row[n + 1];
    float ax = 0.f, ay = 0.f;
    int e = e0 + half;
    // 8-deep batching over stride-2 edges
    for (; e + 14 < e1; e += 16) {
        int sI[8];
        #pragma unroll
        for (int u = 0; u < 8; u++) sI[u] = __ldg(&g_sorted[e + 2 * u]);
        float2 qv[8];
        #pragma unroll
        for (int u = 0; u < 8; u++) qv[u] = __ldg(&g_q[sI[u]]);
        #pragma unroll
        for (int u = 0; u < 8; u++) { ax += qv[u].x; ay += qv[u].y; }
    }
    for (; e < e1; e += 2) {
        float2 qv = __ldg(&g_q[__ldg(&g_sorted[e])]);
        ax += qv.x; ay += qv.y;
    }
    // combine the two halves (lane pair differs only in bit 0)
    ax += __shfl_xor_sync(0xffffffffu, ax, 1);
    ay += __shfl_xor_sync(0xffffffffu, ay, 1);

    float2 qn = g_q[n];
    float dv = g_dinv[n];
    float xax = (ax + qn.x) * dv;
    float xay = (ay + qn.y) * dv;

    // this thread's 32 features: [32*half, 32*half + 32)
    uint4* dst = (uint4*)&g_ph[n * 32];
    #pragma unroll
    for (int c = 0; c < 4; c++) {
        unsigned hh[4];
        #pragma unroll
        for (int j = 0; j < 4; j++) {
            int f = 32 * half + c * 8 + 2 * j;
            float v0 = fmaf(xax, W1s[f],     fmaf(xay, W1s[HID + f],     b1s[f]));
            float v1 = fmaf(xax, W1s[f + 1], fmaf(xay, W1s[HID + f + 1], b1s[f + 1]));
            v0 = fmaxf(v0, 0.0f) * dv;
            v1 = fmaxf(v1, 0.0f) * dv;
            __half2 h2v = __floats2half2_rn(v0, v1);
            hh[j] = *(unsigned*)&h2v;
        }
        uint4 u4;
        u4.x = hh[0]; u4.y = hh[1]; u4.z = hh[2]; u4.w = hh[3];
        dst[4 * half + c] = u4;
    }
}

// Fused: fp16 CSR gather (layer-2 agg) + node-batched h2 GEMV + relu + pool
// + (last block) final FC output + state reset for next replay.
// 256 threads: fg = tid&7 (8 feats), rg = tid>>3; thread handles nodes rg*4+i.
__global__ void __launch_bounds__(256) k_gather2(
        const float* __restrict__ W2, const float* __restrict__ b2,
        const float* __restrict__ Wfc, const float* __restrict__ bfc,
        float* __restrict__ out) {
    __shared__ float  W2s[HID * HID];             // 16 KB, [k*64 + f]
    __shared__ __half hs[TILE2 * HS_STRIDE];      // 16.9 KB
    __shared__ int    sh_last;

    int tid = threadIdx.x;
    int fg = tid & 7, rg = tid >> 3;

    for (int i = tid; i < HID * HID; i += 256) W2s[i] = W2[i];
    float bloc[8];
    #pragma unroll
    for (int j = 0; j < 8; j++) bloc[j] = __ldg(&b2[8 * fg + j]);
    __syncthreads();

    float pool8[8] = {0.f, 0.f, 0.f, 0.f, 0.f, 0.f, 0.f, 0.f};
    const uint4* pt = (const uint4*)g_ph;

    for (int tile = blockIdx.x; tile < NT2; tile += gridDim.x) {
        // -------- stage A: gather agg for 4 nodes, write fp16 to hs --------
        #pragma unroll
        for (int i = 0; i < 4; i++) {
            int nl = rg * 4 + i;
            int n = tile * TILE2 + nl;
            float acc[8] = {0.f, 0.f, 0.f, 0.f, 0.f, 0.f, 0.f, 0.f};
            if (n < NN) {
                int e0 = g_row[n], e1 = g_row[n + 1];
                __half2 pa[4][4];
                #pragma unroll
                for (int j = 0; j < 4; j++)
                    #pragma unroll
                    for (int k = 0; k < 4; k++)
                        pa[j][k] = __floats2half2_rn(0.f, 0.f);
                int e = e0;
                // 8-deep MLP: batch 8 index loads, 8 row loads, then accumulate
                for (; e + 8 <= e1; e += 8) {
                    int sI[8];
                    uint4 r[8];
                    #pragma unroll
                    for (int u = 0; u < 8; u++) sI[u] = __ldg(&g_sorted[e + u]);
                    #pragma unroll
                    for (int u = 0; u < 8; u++) r[u] = __ldg(&pt[sI[u] * 8 + fg]);
                    #pragma unroll
                    for (int u = 0; u < 8; u++) {
                        pa[u & 3][0] = __hadd2(pa[u & 3][0], *(__half2*)&r[u].x);
                        pa[u & 3][1] = __hadd2(pa[u & 3][1], *(__half2*)&r[u].y);
                        pa[u & 3][2] = __hadd2(pa[u & 3][2], *(__half2*)&r[u].z);
                        pa[u & 3][3] = __hadd2(pa[u & 3][3], *(__half2*)&r[u].w);
                    }
                }
                for (; e + 4 <= e1; e += 4) {
                    #pragma unroll
                    for (int u = 0; u < 4; u++) {
                        int sv = __ldg(&g_sorted[e + u]);
                        uint4 r = __ldg(&pt[sv * 8 + fg]);
                        pa[u][0] = __hadd2(pa[u][0], *(__half2*)&r.x);
                        pa[u][1] = __hadd2(pa[u][1], *(__half2*)&r.y);
                        pa[u][2] = __hadd2(pa[u][2], *(__half2*)&r.z);
                        pa[u][3] = __hadd2(pa[u][3], *(__half2*)&r.w);
                    }
                }
                for (; e < e1; e++) {
                    int sv = __ldg(&g_sorted[e]);
                    uint4 r = __ldg(&pt[sv * 8 + fg]);
                    pa[0][0] = __hadd2(pa[0][0], *(__half2*)&r.x);
                    pa[0][1] = __hadd2(pa[0][1], *(__half2*)&r.y);
                    pa[0][2] = __hadd2(pa[0][2], *(__half2*)&r.z);
                    pa[0][3] = __hadd2(pa[0][3], *(__half2*)&r.w);
                }
                #pragma unroll
                for (int j = 0; j < 4; j++) {
                    #pragma unroll
                    for (int k = 0; k < 4; k++) {
                        float2 f2 = __half22float2(pa[j][k]);
                        acc[2 * k]     += f2.x;
                        acc[2 * k + 1] += f2.y;
                    }
                }
                // self loop in fp32
                uint4 rs = pt[n * 8 + fg];
                float2 s0 = __half22float2(*(__half2*)&rs.x);
                float2 s1 = __half22float2(*(__half2*)&rs.y);
                float2 s2 = __half22float2(*(__half2*)&rs.z);
                float2 s3 = __half22float2(*(__half2*)&rs.w);
                acc[0] += s0.x; acc[1] += s0.y; acc[2] += s1.x; acc[3] += s1.y;
                acc[4] += s2.x; acc[5] += s2.y; acc[6] += s3.x; acc[7] += s3.y;
                float sc = g_dinv[n];
                #pragma unroll
                for (int k = 0; k < 8; k++) acc[k] *= sc;
            }
            __half2* hw = (__half2*)&hs[nl * HS_STRIDE + 8 * fg];
            #pragma unroll
            for (int j = 0; j < 4; j++)
                hw[j] = __floats2half2_rn(acc[2 * j], acc[2 * j + 1]);
        }
        __syncthreads();

        // -------- stage B: h2 GEMV for 4 nodes, W2 amortized 4x,
        //          a-values loaded as half2 (k step 2) --------
        float o[4][8];
        #pragma unroll
        for (int i = 0; i < 4; i++)
            #pragma unroll
            for (int j = 0; j < 8; j++) o[i][j] = bloc[j];

        const __half* hp0 = &hs[(rg * 4 + 0) * HS_STRIDE];
        const __half* hp1 = &hs[(rg * 4 + 1) * HS_STRIDE];
        const __half* hp2 = &hs[(rg * 4 + 2) * HS_STRIDE];
        const __half* hp3 = &hs[(rg * 4 + 3) * HS_STRIDE];
        #pragma unroll 2
        for (int k2 = 0; k2 < HID / 2; k2++) {
            float2 a0p = __half22float2(*(const __half2*)&hp0[2 * k2]);
            float2 a1p = __half22float2(*(const __half2*)&hp1[2 * k2]);
            float2 a2p = __half22float2(*(const __half2*)&hp2[2 * k2]);
            float2 a3p = __half22float2(*(const __half2*)&hp3[2 * k2]);
            #pragma unroll
            for (int h = 0; h < 2; h++) {
                int k = 2 * k2 + h;
                float a0 = h ? a0p.y : a0p.x;
                float a1 = h ? a1p.y : a1p.x;
                float a2 = h ? a2p.y : a2p.x;
                float a3 = h ? a3p.y : a3p.x;
                float4 wA = *(const float4*)&W2s[k * HID + 8 * fg];
                float4 wB = *(const float4*)&W2s[k * HID + 8 * fg + 4];
                o[0][0] = fmaf(a0, wA.x, o[0][0]); o[0][1] = fmaf(a0, wA.y, o[0][1]);
                o[0][2] = fmaf(a0, wA.z, o[0][2]); o[0][3] = fmaf(a0, wA.w, o[0][3]);
                o[0][4] = fmaf(a0, wB.x, o[0][4]); o[0][5] = fmaf(a0, wB.y, o[0][5]);
                o[0][6] = fmaf(a0, wB.z, o[0][6]); o[0][7] = fmaf(a0, wB.w, o[0][7]);
                o[1][0] = fmaf(a1, wA.x, o[1][0]); o[1][1] = fmaf(a1, wA.y, o[1][1]);
                o[1][2] = fmaf(a1, wA.z, o[1][2]); o[1][3] = fmaf(a1, wA.w, o[1][3]);
                o[1][4] = fmaf(a1, wB.x, o[1][4]); o[1][5] = fmaf(a1, wB.y, o[1][5]);
                o[1][6] = fmaf(a1, wB.z, o[1][6]); o[1][7] = fmaf(a1, wB.w, o[1][7]);
                o[2][0] = fmaf(a2, wA.x, o[2][0]); o[2][1] = fmaf(a2, wA.y, o[2][1]);
                o[2][2] = fmaf(a2, wA.z, o[2][2]); o[2][3] = fmaf(a2, wA.w, o[2][3]);
                o[2][4] = fmaf(a2, wB.x, o[2][4]); o[2][5] = fmaf(a2, wB.y, o[2][5]);
                o[2][6] = fmaf(a2, wB.z, o[2][6]); o[2][7] = fmaf(a2, wB.w, o[2][7]);
                o[3][0] = fmaf(a3, wA.x, o[3][0]); o[3][1] = fmaf(a3, wA.y, o[3][1]);
                o[3][2] = fmaf(a3, wA.z, o[3][2]); o[3][3] = fmaf(a3, wA.w, o[3][3]);
                o[3][4] = fmaf(a3, wB.x, o[3][4]); o[3][5] = fmaf(a3, wB.y, o[3][5]);
                o[3][6] = fmaf(a3, wB.z, o[3][6]); o[3][7] = fmaf(a3, wB.w, o[3][7]);
            }
        }
        #pragma unroll
        for (int i = 0; i < 4; i++) {
            int n = tile * TILE2 + rg * 4 + i;
            if (n < NN) {
                #pragma unroll
                for (int j = 0; j < 8; j++)
                    pool8[j] += fmaxf(o[i][j], 0.f);
            }
        }
        __syncthreads();   // hs reused next tile
    }

    // -------- final pool reduction (reuse hs as float scratch) --------
    float* hsf = (float*)hs;   // 32*64 floats = 8 KB
    #pragma unroll
    for (int j = 0; j < 8; j++)
        hsf[rg * HID + 8 * fg + j] = pool8[j];
    __syncthreads();
    if (tid < HID) {
        float s = 0.f;
        #pragma unroll 8
        for (int r = 0; r < 32; r++) s += hsf[r * HID + tid];
        atomicAdd(&g_pool[tid], s);
    }

    // -------- last block: final FC output + state reset for next replay ----
    if (tid == 0) {
        __threadfence();
        int t = atomicAdd(&g_done, 1);
        sh_last = (t == gridDim.x - 1);
    }
    __syncthreads();
    if (sh_last) {
        float s = 0.f;
        if (tid < 32) {
            s = g_pool[tid] * __ldg(&Wfc[tid]) + g_pool[tid + 32] * __ldg(&Wfc[tid + 32]);
            #pragma unroll
            for (int o2 = 16; o2 > 0; o2 >>= 1) s += __shfl_down_sync(0xffffffffu, s, o2);
        }
        __syncthreads();               // all reads of g_pool done
        if (tid < HID) g_pool[tid] = 0.f;
        if (tid == 0) {
            g_done = 0;
            out[0] = s * (1.0f / NN) + __ldg(&bfc[0]);
        }
    }
}

// ---------------- launch ----------------
extern "C" void kernel_launch(void* const* d_in, const int* in_sizes, int n_in,
                              void* d_out, int out_size) {
    const float2* x2    = (const float2*)d_in[0];
    const void*   edges = d_in[1];
    const float*  W1    = (const float*)d_in[2];
    const float*  b1    = (const float*)d_in[3];
    const float*  W2    = (const float*)d_in[4];
    const float*  b2    = (const float*)d_in[5];
    const float*  Wfc   = (const float*)d_in[6];
    const float*  bfc   = (const float*)d_in[7];
    float* out = (float*)d_out;

    const int T = 256;
    k_count<<<(NE / 4 + T - 1) / T, T>>>(edges);
    k_scan<<<NBLK1, SCAN_B>>>(x2);
    k_scatter<<<(NE / 4 + T - 1) / T, T>>>(edges);
    k_h1p<<<(NN * 2 + T - 1) / T, T>>>(W1, b1);
    k_gather2<<<NT2, T>>>(W2, b2, Wfc, bfc, out);
}

// round 16
// speedup vs baseline: 1.1016x; 1.0108x over previous
#include <cuda_runtime.h>
#include <cuda_fp16.h>
#include <cstdint>

#define NN 100000
#define NE 3200000
#define HID 64
#define SCAN_B 512
#define NBLK1 ((NN + SCAN_B - 1) / SCAN_B)   // 196
#define TILE2 128
#define NT2 ((NN + TILE2 - 1) / TILE2)       // 782
#define HS_STRIDE 66                          // halves; conflict-free staging
#define ST_AGG  (1 << 28)
#define ST_PRE  (2 << 28)
#define VMASK   0x0FFFFFFF

// ---------------- scratch (device globals; zero-initialized at load) -------
// Pipeline is self-cleaning across graph replays (g_cnt by k_scan, g_part by
// k_scatter, g_pool/g_done by k_gather2's last block).
__device__ int            g_cnt[NN];
__device__ float          g_dinv[NN];
__device__ float2         g_q[NN];         // q = dinv * x (layer-1 gather table)
__device__ int            g_row[NN + 1];   // CSR row pointers (by dst)
__device__ unsigned short g_slot[NE];      // within-bucket slot per edge
__device__ int            g_sorted[NE];    // src ids sorted by dst
__device__ __half2        g_ph[NN * 32];   // p = dinv*relu(h1), fp16, 128 B/node
__device__ float          g_pool[HID];
__device__ int            g_part[NBLK1];   // lookback: status<<28 | value
__device__ int            g_done;

// Detect int64 vs int32 storage from the first 8 qwords.
__device__ __forceinline__ int detect_is64(const void* edges) {
    const unsigned long long* e64 = (const unsigned long long*)edges;
    int is64 = 1;
    #pragma unroll
    for (int k = 0; k < 8; k++)
        if (e64[k] >= (unsigned long long)NN) { is64 = 0; break; }
    return is64;
}

// ---------------- kernels ----------------

// Histogram dst AND record each edge's slot (ushort). 4 edges/thread.
__global__ void k_count(const void* __restrict__ edges) {
    __shared__ int sh_is64;
    if (threadIdx.x == 0) sh_is64 = detect_is64(edges);
    __syncthreads();
    int e0 = (blockIdx.x * blockDim.x + threadIdx.x) * 4;
    if (e0 >= NE) return;
    int d[4];
    if (sh_is64) {
        const longlong2* d2 = (const longlong2*)((const long long*)edges + NE);
        longlong2 a = d2[e0 >> 1], b = d2[(e0 >> 1) + 1];
        d[0] = (int)a.x; d[1] = (int)a.y; d[2] = (int)b.x; d[3] = (int)b.y;
    } else {
        const int4* d4 = (const int4*)((const int*)edges + NE);
        int4 a = d4[e0 >> 2];
        d[0] = a.x; d[1] = a.y; d[2] = a.z; d[3] = a.w;
    }
    ushort4 sl;
    sl.x = (unsigned short)atomicAdd(&g_cnt[d[0]], 1);
    sl.y = (unsigned short)atomicAdd(&g_cnt[d[1]], 1);
    sl.z = (unsigned short)atomicAdd(&g_cnt[d[2]], 1);
    sl.w = (unsigned short)atomicAdd(&g_cnt[d[3]], 1);
    *(ushort4*)&g_slot[e0] = sl;
}

// Single-kernel exclusive scan (decoupled lookback) + dinv + q tables.
// Also re-zeros g_cnt for the next graph replay.
__global__ void __launch_bounds__(SCAN_B) k_scan(const float2* __restrict__ x2) {
    __shared__ int wsum[SCAN_B / 32];
    __shared__ int sh_total, sh_base;
    int bid = blockIdx.x, t = threadIdx.x;
    int i = bid * SCAN_B + t;
    int lane = t & 31, w = t >> 5;

    int v = (i < NN) ? g_cnt[i] : 0;
    int s = v;
    #pragma unroll
    for (int o = 1; o < 32; o <<= 1) {
        int u = __shfl_up_sync(0xffffffffu, s, o);
        if (lane >= o) s += u;
    }
    if (lane == 31) wsum[w] = s;
    __syncthreads();
    if (w == 0) {
        int ws = (lane < SCAN_B / 32) ? wsum[lane] : 0;
        #pragma unroll
        for (int o = 1; o < 16; o <<= 1) {
            int u = __shfl_up_sync(0xffffffffu, ws, o);
            if (lane >= o) ws += u;
        }
        if (lane < SCAN_B / 32) wsum[lane] = ws;
    }
    __syncthreads();
    int base_l = (w > 0) ? wsum[w - 1] : 0;
    int incl = s + base_l;                 // inclusive within block
    if (t == SCAN_B - 1) sh_total = incl;
    __syncthreads();
    int total = sh_total;

    if (t == 0) {
        int pk = (bid == 0) ? (ST_PRE | total) : (ST_AGG | total);
        *(volatile int*)&g_part[bid] = pk;
        __threadfence();
    }

    if (bid == 0) {
        if (t == 0) sh_base = 0;
    } else if (w == 0) {
        int run = 0, lag = 1;
        for (;;) {
            int idx = bid - lag - lane;
            int pv = (idx >= 0) ? *(volatile int*)&g_part[idx] : ST_PRE;
            if (!__all_sync(0xffffffffu, (pv & ~VMASK) != 0)) continue;
            unsigned pm = __ballot_sync(0xffffffffu, (pv & ~VMASK) == ST_PRE);
            int val = pv & VMASK;
            if (pm) {
                int pl = __ffs(pm) - 1;
                int c = (lane <= pl) ? val : 0;
                #pragma unroll
                for (int o = 16; o > 0; o >>= 1) c += __shfl_xor_sync(0xffffffffu, c, o);
                run += c;
                break;
            } else {
                int c = val;
                #pragma unroll
                for (int o = 16; o > 0; o >>= 1) c += __shfl_xor_sync(0xffffffffu, c, o);
                run += c;
                lag += 32;
            }
        }
        if (lane == 0) {
            *(volatile int*)&g_part[bid] = ST_PRE | ((run + total) & VMASK);
            __threadfence();
            sh_base = run;
        }
    }
    __syncthreads();
    int base_g = sh_base;

    if (i < NN) {
        g_row[i] = base_g + incl - v;      // exclusive global prefix
        g_cnt[i] = 0;                      // self-clean for next replay
        float d = rsqrtf((float)v + 1.0f);
        g_dinv[i] = d;
        float2 xv = x2[i];
        g_q[i] = make_float2(xv.x * d, xv.y * d);
    }
    if (bid == 0 && t == 0) g_row[NN] = NE;
}

// Atomic-free counting-sort scatter: addr = row[dst] + slot[e]. 4 edges/thread.
// Block 0 also re-zeros g_part (scan is fully done by now).
__global__ void k_scatter(const void* __restrict__ edges) {
    __shared__ int sh_is64;
    if (threadIdx.x == 0) sh_is64 = detect_is64(edges);
    __syncthreads();
    if (blockIdx.x == 0 && threadIdx.x < NBLK1) g_part[threadIdx.x] = 0;

    int e0 = (blockIdx.x * blockDim.x + threadIdx.x) * 4;
    if (e0 >= NE) return;
    int s[4], d[4];
    if (sh_is64) {
        const longlong2* sp = (const longlong2*)edges;
        const longlong2* dp = (const longlong2*)((const long long*)edges + NE);
        longlong2 sa = sp[e0 >> 1], sb = sp[(e0 >> 1) + 1];
        longlong2 da = dp[e0 >> 1], db = dp[(e0 >> 1) + 1];
        s[0] = (int)sa.x; s[1] = (int)sa.y; s[2] = (int)sb.x; s[3] = (int)sb.y;
        d[0] = (int)da.x; d[1] = (int)da.y; d[2] = (int)db.x; d[3] = (int)db.y;
    } else {
        const int4* sp = (const int4*)edges;
        const int4* dp = (const int4*)((const int*)edges + NE);
        int4 sa = sp[e0 >> 2], da = dp[e0 >> 2];
        s[0] = sa.x; s[1] = sa.y; s[2] = sa.z; s[3] = sa.w;
        d[0] = da.x; d[1] = da.y; d[2] = da.z; d[3] = da.w;
    }
    ushort4 sl = *(const ushort4*)&g_slot[e0];
    g_sorted[__ldg(&g_row[d[0]]) + sl.x] = s[0];
    g_sorted[__ldg(&g_row[d[1]]) + sl.y] = s[1];
    g_sorted[__ldg(&g_row[d[2]]) + sl.z] = s[2];
    g_sorted[__ldg(&g_row[d[3]]) + sl.w] = s[3];
}

// Four threads per node: thread q sums edges e0+q, e0+q+4, ... (8-deep
// batching; the node's 4 threads read contiguous g_sorted words each step).
// Two shfl_xor combine; each thread emits 16 of the 64 fp16 features.
__global__ void __launch_bounds__(256) k_h1p(const float* __restrict__ W1,
                                             const float* __restrict__ b1) {
    __shared__ float W1s[2 * HID];
    __shared__ float b1s[HID];
    int tid = threadIdx.x;
    if (tid < 2 * HID) W1s[tid] = W1[tid];
    if (tid < HID) b1s[tid] = b1[tid];
    __syncthreads();

    int gt = blockIdx.x * blockDim.x + tid;
    int n = gt >> 2;
    if (n >= NN) return;
    int quar = gt & 3;

    int e0 = g_row[n], e1 = g_row[n + 1];
    float ax = 0.f, ay = 0.f;
    int e = e0 + quar;
    // 8-deep batching over stride-4 edges (32-edge span per iteration)
    for (; e + 28 < e1; e += 32) {
        int sI[8];
        #pragma unroll
        for (int u = 0; u < 8; u++) sI[u] = __ldg(&g_sorted[e + 4 * u]);
        float2 qv[8];
        #pragma unroll
        for (int u = 0; u < 8; u++) qv[u] = __ldg(&g_q[sI[u]]);
        #pragma unroll
        for (int u = 0; u < 8; u++) { ax += qv[u].x; ay += qv[u].y; }
    }
    for (; e < e1; e += 4) {
        float2 qv = __ldg(&g_q[__ldg(&g_sorted[e])]);
        ax += qv.x; ay += qv.y;
    }
    // combine across the aligned quad (lanes differ in bits 0-1)
    ax += __shfl_xor_sync(0xffffffffu, ax, 1);
    ay += __shfl_xor_sync(0xffffffffu, ay, 1);
    ax += __shfl_xor_sync(0xffffffffu, ax, 2);
    ay += __shfl_xor_sync(0xffffffffu, ay, 2);

    float2 qn = g_q[n];
    float dv = g_dinv[n];
    float xax = (ax + qn.x) * dv;
    float xay = (ay + qn.y) * dv;

    // this thread's 16 features: [16*quar, 16*quar + 16)
    uint4* dst = (uint4*)&g_ph[n * 32];
    #pragma unroll
    for (int c = 0; c < 2; c++) {
        unsigned hh[4];
        #pragma unroll
        for (int j = 0; j < 4; j++) {
            int f = 16 * quar + c * 8 + 2 * j;
            float v0 = fmaf(xax, W1s[f],     fmaf(xay, W1s[HID + f],     b1s[f]));
            float v1 = fmaf(xax, W1s[f + 1], fmaf(xay, W1s[HID + f + 1], b1s[f + 1]));
            v0 = fmaxf(v0, 0.0f) * dv;
            v1 = fmaxf(v1, 0.0f) * dv;
            __half2 h2v = __floats2half2_rn(v0, v1);
            hh[j] = *(unsigned*)&h2v;
        }
        uint4 u4;
        u4.x = hh[0]; u4.y = hh[1]; u4.z = hh[2]; u4.w = hh[3];
        dst[2 * quar + c] = u4;
    }
}

// Fused: fp16 CSR gather (layer-2 agg) + node-batched h2 GEMV + relu + pool
// + (last block) final FC output + state reset for next replay.
// 256 threads: fg = tid&7 (8 feats), rg = tid>>3; thread handles nodes rg*4+i.
__global__ void __launch_bounds__(256) k_gather2(
        const float* __restrict__ W2, const float* __restrict__ b2,
        const float* __restrict__ Wfc, const float* __restrict__ bfc,
        float* __restrict__ out) {
    __shared__ float  W2s[HID * HID];             // 16 KB, [k*64 + f]
    __shared__ __half hs[TILE2 * HS_STRIDE];      // 16.9 KB
    __shared__ int    sh_last;

    int tid = threadIdx.x;
    int fg = tid & 7, rg = tid >> 3;

    for (int i = tid; i < HID * HID; i += 256) W2s[i] = W2[i];
    float bloc[8];
    #pragma unroll
    for (int j = 0; j < 8; j++) bloc[j] = __ldg(&b2[8 * fg + j]);
    __syncthreads();

    float pool8[8] = {0.f, 0.f, 0.f, 0.f, 0.f, 0.f, 0.f, 0.f};
    const uint4* pt = (const uint4*)g_ph;

    for (int tile = blockIdx.x; tile < NT2; tile += gridDim.x) {
        // -------- stage A: gather agg for 4 nodes, write fp16 to hs --------
        #pragma unroll
        for (int i = 0; i < 4; i++) {
            int nl = rg * 4 + i;
            int n = tile * TILE2 + nl;
            float acc[8] = {0.f, 0.f, 0.f, 0.f, 0.f, 0.f, 0.f, 0.f};
            if (n < NN) {
                int e0 = g_row[n], e1 = g_row[n + 1];
                __half2 pa[4][4];
                #pragma unroll
                for (int j = 0; j < 4; j++)
                    #pragma unroll
                    for (int k = 0; k < 4; k++)
                        pa[j][k] = __floats2half2_rn(0.f, 0.f);
                int e = e0;
                // 8-deep MLP: batch 8 index loads, 8 row loads, then accumulate
                for (; e + 8 <= e1; e += 8) {
                    int sI[8];
                    uint4 r[8];
                    #pragma unroll
                    for (int u = 0; u < 8; u++) sI[u] = __ldg(&g_sorted[e + u]);
                    #pragma unroll
                    for (int u = 0; u < 8; u++) r[u] = __ldg(&pt[sI[u] * 8 + fg]);
                    #pragma unroll
                    for (int u = 0; u < 8; u++) {
                        pa[u & 3][0] = __hadd2(pa[u & 3][0], *(__half2*)&r[u].x);
                        pa[u & 3][1] = __hadd2(pa[u & 3][1], *(__half2*)&r[u].y);
                        pa[u & 3][2] = __hadd2(pa[u & 3][2], *(__half2*)&r[u].z);
                        pa[u & 3][3] = __hadd2(pa[u & 3][3], *(__half2*)&r[u].w);
                    }
                }
                for (; e + 4 <= e1; e += 4) {
                    #pragma unroll
                    for (int u = 0; u < 4; u++) {
                        int sv = __ldg(&g_sorted[e + u]);
                        uint4 r = __ldg(&pt[sv * 8 + fg]);
                        pa[u][0] = __hadd2(pa[u][0], *(__half2*)&r.x);
                        pa[u][1] = __hadd2(pa[u][1], *(__half2*)&r.y);
                        pa[u][2] = __hadd2(pa[u][2], *(__half2*)&r.z);
                        pa[u][3] = __hadd2(pa[u][3], *(__half2*)&r.w);
                    }
                }
                for (; e < e1; e++) {
                    int sv = __ldg(&g_sorted[e]);
                    uint4 r = __ldg(&pt[sv * 8 + fg]);
                    pa[0][0] = __hadd2(pa[0][0], *(__half2*)&r.x);
                    pa[0][1] = __hadd2(pa[0][1], *(__half2*)&r.y);
                    pa[0][2] = __hadd2(pa[0][2], *(__half2*)&r.z);
                    pa[0][3] = __hadd2(pa[0][3], *(__half2*)&r.w);
                }
                #pragma unroll
                for (int j = 0; j < 4; j++) {
                    #pragma unroll
                    for (int k = 0; k < 4; k++) {
                        float2 f2 = __half22float2(pa[j][k]);
                        acc[2 * k]     += f2.x;
                        acc[2 * k + 1] += f2.y;
                    }
                }
                // self loop in fp32
                uint4 rs = pt[n * 8 + fg];
                float2 s0 = __half22float2(*(__half2*)&rs.x);
                float2 s1 = __half22float2(*(__half2*)&rs.y);
                float2 s2 = __half22float2(*(__half2*)&rs.z);
                float2 s3 = __half22float2(*(__half2*)&rs.w);
                acc[0] += s0.x; acc[1] += s0.y; acc[2] += s1.x; acc[3] += s1.y;
                acc[4] += s2.x; acc[5] += s2.y; acc[6] += s3.x; acc[7] += s3.y;
                float sc = g_dinv[n];
                #pragma unroll
                for (int k = 0; k < 8; k++) acc[k] *= sc;
            }
            __half2* hw = (__half2*)&hs[nl * HS_STRIDE + 8 * fg];
            #pragma unroll
            for (int j = 0; j < 4; j++)
                hw[j] = __floats2half2_rn(acc[2 * j], acc[2 * j + 1]);
        }
        __syncthreads();

        // -------- stage B: h2 GEMV for 4 nodes, W2 amortized 4x,
        //          a-values loaded as half2 (k step 2) --------
        float o[4][8];
        #pragma unroll
        for (int i = 0; i < 4; i++)
            #pragma unroll
            for (int j = 0; j < 8; j++) o[i][j] = bloc[j];

        const __half* hp0 = &hs[(rg * 4 + 0) * HS_STRIDE];
        const __half* hp1 = &hs[(rg * 4 + 1) * HS_STRIDE];
        const __half* hp2 = &hs[(rg * 4 + 2) * HS_STRIDE];
        const __half* hp3 = &hs[(rg * 4 + 3) * HS_STRIDE];
        #pragma unroll 2
        for (int k2 = 0; k2 < HID / 2; k2++) {
            float2 a0p = __half22float2(*(const __half2*)&hp0[2 * k2]);
            float2 a1p = __half22float2(*(const __half2*)&hp1[2 * k2]);
            float2 a2p = __half22float2(*(const __half2*)&hp2[2 * k2]);
            float2 a3p = __half22float2(*(const __half2*)&hp3[2 * k2]);
            #pragma unroll
            for (int h = 0; h < 2; h++) {
                int k = 2 * k2 + h;
                float a0 = h ? a0p.y : a0p.x;
                float a1 = h ? a1p.y : a1p.x;
                float a2 = h ? a2p.y : a2p.x;
                float a3 = h ? a3p.y : a3p.x;
                float4 wA = *(const float4*)&W2s[k * HID + 8 * fg];
                float4 wB = *(const float4*)&W2s[k * HID + 8 * fg + 4];
                o[0][0] = fmaf(a0, wA.x, o[0][0]); o[0][1] = fmaf(a0, wA.y, o[0][1]);
                o[0][2] = fmaf(a0, wA.z, o[0][2]); o[0][3] = fmaf(a0, wA.w, o[0][3]);
                o[0][4] = fmaf(a0, wB.x, o[0][4]); o[0][5] = fmaf(a0, wB.y, o[0][5]);
                o[0][6] = fmaf(a0, wB.z, o[0][6]); o[0][7] = fmaf(a0, wB.w, o[0][7]);
                o[1][0] = fmaf(a1, wA.x, o[1][0]); o[1][1] = fmaf(a1, wA.y, o[1][1]);
                o[1][2] = fmaf(a1, wA.z, o[1][2]); o[1][3] = fmaf(a1, wA.w, o[1][3]);
                o[1][4] = fmaf(a1, wB.x, o[1][4]); o[1][5] = fmaf(a1, wB.y, o[1][5]);
                o[1][6] = fmaf(a1, wB.z, o[1][6]); o[1][7] = fmaf(a1, wB.w, o[1][7]);
                o[2][0] = fmaf(a2, wA.x, o[2][0]); o[2][1] = fmaf(a2, wA.y, o[2][1]);
                o[2][2] = fmaf(a2, wA.z, o[2][2]); o[2][3] = fmaf(a2, wA.w, o[2][3]);
                o[2][4] = fmaf(a2, wB.x, o[2][4]); o[2][5] = fmaf(a2, wB.y, o[2][5]);
                o[2][6] = fmaf(a2, wB.z, o[2][6]); o[2][7] = fmaf(a2, wB.w, o[2][7]);
                o[3][0] = fmaf(a3, wA.x, o[3][0]); o[3][1] = fmaf(a3, wA.y, o[3][1]);
                o[3][2] = fmaf(a3, wA.z, o[3][2]); o[3][3] = fmaf(a3, wA.w, o[3][3]);
                o[3][4] = fmaf(a3, wB.x, o[3][4]); o[3][5] = fmaf(a3, wB.y, o[3][5]);
                o[3][6] = fmaf(a3, wB.z, o[3][6]); o[3][7] = fmaf(a3, wB.w, o[3][7]);
            }
        }
        #pragma unroll
        for (int i = 0; i < 4; i++) {
            int n = tile * TILE2 + rg * 4 + i;
            if (n < NN) {
                #pragma unroll
                for (int j = 0; j < 8; j++)
                    pool8[j] += fmaxf(o[i][j], 0.f);
            }
        }
        __syncthreads();   // hs reused next tile
    }

    // -------- final pool reduction (reuse hs as float scratch) --------
    float* hsf = (float*)hs;   // 32*64 floats = 8 KB
    #pragma unroll
    for (int j = 0; j < 8; j++)
        hsf[rg * HID + 8 * fg + j] = pool8[j];
    __syncthreads();
    if (tid < HID) {
        float s = 0.f;
        #pragma unroll 8
        for (int r = 0; r < 32; r++) s += hsf[r * HID + tid];
        atomicAdd(&g_pool[tid], s);
    }

    // -------- last block: final FC output + state reset for next replay ----
    if (tid == 0) {
        __threadfence();
        int t = atomicAdd(&g_done, 1);
        sh_last = (t == gridDim.x - 1);
    }
    __syncthreads();
    if (sh_last) {
        float s = 0.f;
        if (tid < 32) {
            s = g_pool[tid] * __ldg(&Wfc[tid]) + g_pool[tid + 32] * __ldg(&Wfc[tid + 32]);
            #pragma unroll
            for (int o2 = 16; o2 > 0; o2 >>= 1) s += __shfl_down_sync(0xffffffffu, s, o2);
        }
        __syncthreads();               // all reads of g_pool done
        if (tid < HID) g_pool[tid] = 0.f;
        if (tid == 0) {
            g_done = 0;
            out[0] = s * (1.0f / NN) + __ldg(&bfc[0]);
        }
    }
}

// ---------------- launch ----------------
extern "C" void kernel_launch(void* const* d_in, const int* in_sizes, int n_in,
                              void* d_out, int out_size) {
    const float2* x2    = (const float2*)d_in[0];
    const void*   edges = d_in[1];
    const float*  W1    = (const float*)d_in[2];
    const float*  b1    = (const float*)d_in[3];
    const float*  W2    = (const float*)d_in[4];
    const float*  b2    = (const float*)d_in[5];
    const float*  Wfc   = (const float*)d_in[6];
    const float*  bfc   = (const float*)d_in[7];
    float* out = (float*)d_out;

    const int T = 256;
    k_count<<<(NE / 4 + T - 1) / T, T>>>(edges);
    k_scan<<<NBLK1, SCAN_B>>>(x2);
    k_scatter<<<(NE / 4 + T - 1) / T, T>>>(edges);
    k_h1p<<<(NN * 4 + T - 1) / T, T>>>(W1, b1);
    k_gather2<<<NT2, T>>>(W2, b2, Wfc, bfc, out);
}

// round 17
// speedup vs baseline: 1.1382x; 1.0333x over previous
#include <cuda_runtime.h>
#include <cuda_fp16.h>
#include <cstdint>

#define NN 100000
#define NE 3200000
#define HID 64
#define SCAN_B 512
#define NBLK1 ((NN + SCAN_B - 1) / SCAN_B)   // 196
#define TILE2 128
#define NT2 ((NN + TILE2 - 1) / TILE2)       // 782
#define HS_STRIDE 66                          // halves; conflict-free staging
#define ES_CAP 4608                           // mean 4096 + 8 sigma
#define ST_AGG  (1 << 28)
#define ST_PRE  (2 << 28)
#define VMASK   0x0FFFFFFF

// dynamic smem partition (bytes)
#define SM_W2   0
#define SM_HS   (HID * HID * 4)                       // 16384
#define SM_ES   (SM_HS + TILE2 * HS_STRIDE * 2)       // 16384+16896=33280
#define SM_TOT  (SM_ES + ES_CAP * 4)                  // 51712

// ---------------- scratch (device globals; zero-initialized at load) -------
__device__ int            g_cnt[NN];
__device__ float          g_dinv[NN];
__device__ float2         g_q[NN];         // q = dinv * x (layer-1 gather table)
__device__ int            g_row[NN + 1];   // CSR row pointers (by dst)
__device__ unsigned short g_slot[NE];      // within-bucket slot per edge
__device__ int            g_sorted[NE];    // src ids sorted by dst
__device__ __half2        g_ph[NN * 32];   // p = dinv*relu(h1), fp16, 128 B/node
__device__ float          g_pool[HID];
__device__ int            g_part[NBLK1];   // lookback: status<<28 | value
__device__ int            g_done;

__device__ __forceinline__ int detect_is64(const void* edges) {
    const unsigned long long* e64 = (const unsigned long long*)edges;
    int is64 = 1;
    #pragma unroll
    for (int k = 0; k < 8; k++)
        if (e64[k] >= (unsigned long long)NN) { is64 = 0; break; }
    return is64;
}

// ---------------- kernels ----------------

__global__ void k_count(const void* __restrict__ edges) {
    __shared__ int sh_is64;
    if (threadIdx.x == 0) sh_is64 = detect_is64(edges);
    __syncthreads();
    int e0 = (blockIdx.x * blockDim.x + threadIdx.x) * 4;
    if (e0 >= NE) return;
    int d[4];
    if (sh_is64) {
        const longlong2* d2 = (const longlong2*)((const long long*)edges + NE);
        longlong2 a = d2[e0 >> 1], b = d2[(e0 >> 1) + 1];
        d[0] = (int)a.x; d[1] = (int)a.y; d[2] = (int)b.x; d[3] = (int)b.y;
    } else {
        const int4* d4 = (const int4*)((const int*)edges + NE);
        int4 a = d4[e0 >> 2];
        d[0] = a.x; d[1] = a.y; d[2] = a.z; d[3] = a.w;
    }
    ushort4 sl;
    sl.x = (unsigned short)atomicAdd(&g_cnt[d[0]], 1);
    sl.y = (unsigned short)atomicAdd(&g_cnt[d[1]], 1);
    sl.z = (unsigned short)atomicAdd(&g_cnt[d[2]], 1);
    sl.w = (unsigned short)atomicAdd(&g_cnt[d[3]], 1);
    *(ushort4*)&g_slot[e0] = sl;
}

__global__ void __launch_bounds__(SCAN_B) k_scan(const float2* __restrict__ x2) {
    __shared__ int wsum[SCAN_B / 32];
    __shared__ int sh_total, sh_base;
    int bid = blockIdx.x, t = threadIdx.x;
    int i = bid * SCAN_B + t;
    int lane = t & 31, w = t >> 5;

    int v = (i < NN) ? g_cnt[i] : 0;
    int s = v;
    #pragma unroll
    for (int o = 1; o < 32; o <<= 1) {
        int u = __shfl_up_sync(0xffffffffu, s, o);
        if (lane >= o) s += u;
    }
    if (lane == 31) wsum[w] = s;
    __syncthreads();
    if (w == 0) {
        int ws = (lane < SCAN_B / 32) ? wsum[lane] : 0;
        #pragma unroll
        for (int o = 1; o < 16; o <<= 1) {
            int u = __shfl_up_sync(0xffffffffu, ws, o);
            if (lane >= o) ws += u;
        }
        if (lane < SCAN_B / 32) wsum[lane] = ws;
    }
    __syncthreads();
    int base_l = (w > 0) ? wsum[w - 1] : 0;
    int incl = s + base_l;
    if (t == SCAN_B - 1) sh_total = incl;
    __syncthreads();
    int total = sh_total;

    if (t == 0) {
        int pk = (bid == 0) ? (ST_PRE | total) : (ST_AGG | total);
        *(volatile int*)&g_part[bid] = pk;
        __threadfence();
    }

    if (bid == 0) {
        if (t == 0) sh_base = 0;
    } else if (w == 0) {
        int run = 0, lag = 1;
        for (;;) {
            int idx = bid - lag - lane;
            int pv = (idx >= 0) ? *(volatile int*)&g_part[idx] : ST_PRE;
            if (!__all_sync(0xffffffffu, (pv & ~VMASK) != 0)) continue;
            unsigned pm = __ballot_sync(0xffffffffu, (pv & ~VMASK) == ST_PRE);
            int val = pv & VMASK;
            if (pm) {
                int pl = __ffs(pm) - 1;
                int c = (lane <= pl) ? val : 0;
                #pragma unroll
                for (int o = 16; o > 0; o >>= 1) c += __shfl_xor_sync(0xffffffffu, c, o);
                run += c;
                break;
            } else {
                int c = val;
                #pragma unroll
                for (int o = 16; o > 0; o >>= 1) c += __shfl_xor_sync(0xffffffffu, c, o);
                run += c;
                lag += 32;
            }
        }
        if (lane == 0) {
            *(volatile int*)&g_part[bid] = ST_PRE | ((run + total) & VMASK);
            __threadfence();
            sh_base = run;
        }
    }
    __syncthreads();
    int base_g = sh_base;

    if (i < NN) {
        g_row[i] = base_g + incl - v;
        g_cnt[i] = 0;                      // self-clean for next replay
        float d = rsqrtf((float)v + 1.0f);
        g_dinv[i] = d;
        float2 xv = x2[i];
        g_q[i] = make_float2(xv.x * d, xv.y * d);
    }
    if (bid == 0 && t == 0) g_row[NN] = NE;
}

__global__ void k_scatter(const void* __restrict__ edges) {
    __shared__ int sh_is64;
    if (threadIdx.x == 0) sh_is64 = detect_is64(edges);
    __syncthreads();
    if (blockIdx.x == 0 && threadIdx.x < NBLK1) g_part[threadIdx.x] = 0;

    int e0 = (blockIdx.x * blockDim.x + threadIdx.x) * 4;
    if (e0 >= NE) return;
    int s[4], d[4];
    if (sh_is64) {
        const longlong2* sp = (const longlong2*)edges;
        const longlong2* dp = (const longlong2*)((const long long*)edges + NE);
        longlong2 sa = sp[e0 >> 1], sb = sp[(e0 >> 1) + 1];
        longlong2 da = dp[e0 >> 1], db = dp[(e0 >> 1) + 1];
        s[0] = (int)sa.x; s[1] = (int)sa.y; s[2] = (int)sb.x; s[3] = (int)sb.y;
        d[0] = (int)da.x; d[1] = (int)da.y; d[2] = (int)db.x; d[3] = (int)db.y;
    } else {
        const int4* sp = (const int4*)edges;
        const int4* dp = (const int4*)((const int*)edges + NE);
        int4 sa = sp[e0 >> 2], da = dp[e0 >> 2];
        s[0] = sa.x; s[1] = sa.y; s[2] = sa.z; s[3] = sa.w;
        d[0] = da.x; d[1] = da.y; d[2] = da.z; d[3] = da.w;
    }
    ushort4 sl = *(const ushort4*)&g_slot[e0];
    g_sorted[__ldg(&g_row[d[0]]) + sl.x] = s[0];
    g_sorted[__ldg(&g_row[d[1]]) + sl.y] = s[1];
    g_sorted[__ldg(&g_row[d[2]]) + sl.z] = s[2];
    g_sorted[__ldg(&g_row[d[3]]) + sl.w] = s[3];
}

// Four threads per node (stride-4 edges, 8-deep batching, 2 shfl combine);
// each thread emits 16 of the 64 fp16 features.
__global__ void __launch_bounds__(256) k_h1p(const float* __restrict__ W1,
                                             const float* __restrict__ b1) {
    __shared__ float W1s[2 * HID];
    __shared__ float b1s[HID];
    int tid = threadIdx.x;
    if (tid < 2 * HID) W1s[tid] = W1[tid];
    if (tid < HID) b1s[tid] = b1[tid];
    __syncthreads();

    int gt = blockIdx.x * blockDim.x + tid;
    int n = gt >> 2;
    if (n >= NN) return;
    int quar = gt & 3;

    int e0 = g_row[n], e1 = g_row[n + 1];
    float ax = 0.f, ay = 0.f;
    int e = e0 + quar;
    for (; e + 28 < e1; e += 32) {
        int sI[8];
        #pragma unroll
        for (int u = 0; u < 8; u++) sI[u] = __ldg(&g_sorted[e + 4 * u]);
        float2 qv[8];
        #pragma unroll
        for (int u = 0; u < 8; u++) qv[u] = __ldg(&g_q[sI[u]]);
        #pragma unroll
        for (int u = 0; u < 8; u++) { ax += qv[u].x; ay += qv[u].y; }
    }
    for (; e < e1; e += 4) {
        float2 qv = __ldg(&g_q[__ldg(&g_sorted[e])]);
        ax += qv.x; ay += qv.y;
    }
    ax += __shfl_xor_sync(0xffffffffu, ax, 1);
    ay += __shfl_xor_sync(0xffffffffu, ay, 1);
    ax += __shfl_xor_sync(0xffffffffu, ax, 2);
    ay += __shfl_xor_sync(0xffffffffu, ay, 2);

    float2 qn = g_q[n];
    float dv = g_dinv[n];
    float xax = (ax + qn.x) * dv;
    float xay = (ay + qn.y) * dv;

    uint4* dst = (uint4*)&g_ph[n * 32];
    #pragma unroll
    for (int c = 0; c < 2; c++) {
        unsigned hh[4];
        #pragma unroll
        for (int j = 0; j < 4; j++) {
            int f = 16 * quar + c * 8 + 2 * j;
            float v0 = fmaf(xax, W1s[f],     fmaf(xay, W1s[HID + f],     b1s[f]));
            float v1 = fmaf(xax, W1s[f + 1], fmaf(xay, W1s[HID + f + 1], b1s[f + 1]));
            v0 = fmaxf(v0, 0.0f) * dv;
            v1 = fmaxf(v1, 0.0f) * dv;
            __half2 h2v = __floats2half2_rn(v0, v1);
            hh[j] = *(unsigned*)&h2v;
        }
        uint4 u4;
        u4.x = hh[0]; u4.y = hh[1]; u4.z = hh[2]; u4.w = hh[3];
        dst[2 * quar + c] = u4;
    }
}

// Fused: fp16 CSR gather (layer-2 agg, tile edge indices staged in smem) +
// node-batched h2 GEMV + relu + pool + (last block) final FC + state reset.
// 256 threads: fg = tid&7 (8 feats), rg = tid>>3; thread handles nodes rg*4+i.
// Dynamic smem: W2s | hs | es (51.7 KB).
__global__ void __launch_bounds__(256) k_gather2(
        const float* __restrict__ W2, const float* __restrict__ b2,
        const float* __restrict__ Wfc, const float* __restrict__ bfc,
        float* __restrict__ out) {
    extern __shared__ char dsm[];
    float*  W2s = (float*)(dsm + SM_W2);
    __half* hs  = (__half*)(dsm + SM_HS);
    int*    es  = (int*)(dsm + SM_ES);
    __shared__ int sh_last;

    int tid = threadIdx.x;
    int fg = tid & 7, rg = tid >> 3;

    for (int i = tid; i < HID * HID; i += 256) W2s[i] = W2[i];
    float bloc[8];
    #pragma unroll
    for (int j = 0; j < 8; j++) bloc[j] = __ldg(&b2[8 * fg + j]);

    float pool8[8] = {0.f, 0.f, 0.f, 0.f, 0.f, 0.f, 0.f, 0.f};
    const uint4* pt = (const uint4*)g_ph;

    for (int tile = blockIdx.x; tile < NT2; tile += gridDim.x) {
        int nhi = tile * TILE2 + TILE2;
        if (nhi > NN) nhi = NN;
        int te0 = __ldg(&g_row[tile * TILE2]);
        int te1 = __ldg(&g_row[nhi]);
        int tcnt = te1 - te0;
        // cooperative coalesced staging of this tile's edge indices
        int ncap = (tcnt <= ES_CAP) ? tcnt : 0;   // overflow -> global path
        for (int i = tid; i < ncap; i += 256) es[i] = g_sorted[te0 + i];
        __syncthreads();
        const int* idxp = ncap ? es : (g_sorted + te0);

        // -------- stage A: gather agg for 4 nodes, write fp16 to hs --------
        #pragma unroll
        for (int i = 0; i < 4; i++) {
            int nl = rg * 4 + i;
            int n = tile * TILE2 + nl;
            float acc[8] = {0.f, 0.f, 0.f, 0.f, 0.f, 0.f, 0.f, 0.f};
            if (n < NN) {
                int e0 = g_row[n] - te0, e1 = g_row[n + 1] - te0;  // local
                __half2 pa[4][4];
                #pragma unroll
                for (int j = 0; j < 4; j++)
                    #pragma unroll
                    for (int k = 0; k < 4; k++)
                        pa[j][k] = __floats2half2_rn(0.f, 0.f);
                int e = e0;
                for (; e + 8 <= e1; e += 8) {
                    int sI[8];
                    uint4 r[8];
                    #pragma unroll
                    for (int u = 0; u < 8; u++) sI[u] = idxp[e + u];
                    #pragma unroll
                    for (int u = 0; u < 8; u++) r[u] = __ldg(&pt[sI[u] * 8 + fg]);
                    #pragma unroll
                    for (int u = 0; u < 8; u++) {
                        pa[u & 3][0] = __hadd2(pa[u & 3][0], *(__half2*)&r[u].x);
                        pa[u & 3][1] = __hadd2(pa[u & 3][1], *(__half2*)&r[u].y);
                        pa[u & 3][2] = __hadd2(pa[u & 3][2], *(__half2*)&r[u].z);
                        pa[u & 3][3] = __hadd2(pa[u & 3][3], *(__half2*)&r[u].w);
                    }
                }
                for (; e < e1; e++) {
                    int sv = idxp[e];
                    uint4 r = __ldg(&pt[sv * 8 + fg]);
                    pa[0][0] = __hadd2(pa[0][0], *(__half2*)&r.x);
                    pa[0][1] = __hadd2(pa[0][1], *(__half2*)&r.y);
                    pa[0][2] = __hadd2(pa[0][2], *(__half2*)&r.z);
                    pa[0][3] = __hadd2(pa[0][3], *(__half2*)&r.w);
                }
                #pragma unroll
                for (int j = 0; j < 4; j++) {
                    #pragma unroll
                    for (int k = 0; k < 4; k++) {
                        float2 f2 = __half22float2(pa[j][k]);
                        acc[2 * k]     += f2.x;
                        acc[2 * k + 1] += f2.y;
                    }
                }
                // self loop in fp32
                uint4 rs = pt[n * 8 + fg];
                float2 s0 = __half22float2(*(__half2*)&rs.x);
                float2 s1 = __half22float2(*(__half2*)&rs.y);
                float2 s2 = __half22float2(*(__half2*)&rs.z);
                float2 s3 = __half22float2(*(__half2*)&rs.w);
                acc[0] += s0.x; acc[1] += s0.y; acc[2] += s1.x; acc[3] += s1.y;
                acc[4] += s2.x; acc[5] += s2.y; acc[6] += s3.x; acc[7] += s3.y;
                float sc = g_dinv[n];
                #pragma unroll
                for (int k = 0; k < 8; k++) acc[k] *= sc;
            }
            __half2* hw = (__half2*)&hs[nl * HS_STRIDE + 8 * fg];
            #pragma unroll
            for (int j = 0; j < 4; j++)
                hw[j] = __floats2half2_rn(acc[2 * j], acc[2 * j + 1]);
        }
        __syncthreads();

        // -------- stage B: h2 GEMV for 4 nodes, W2 amortized 4x --------
        float o[4][8];
        #pragma unroll
        for (int i = 0; i < 4; i++)
            #pragma unroll
            for (int j = 0; j < 8; j++) o[i][j] = bloc[j];

        const __half* hp0 = &hs[(rg * 4 + 0) * HS_STRIDE];
        const __half* hp1 = &hs[(rg * 4 + 1) * HS_STRIDE];
        const __half* hp2 = &hs[(rg * 4 + 2) * HS_STRIDE];
        const __half* hp3 = &hs[(rg * 4 + 3) * HS_STRIDE];
        #pragma unroll 2
        for (int k2 = 0; k2 < HID / 2; k2++) {
            float2 a0p = __half22float2(*(const __half2*)&hp0[2 * k2]);
            float2 a1p = __half22float2(*(const __half2*)&hp1[2 * k2]);
            float2 a2p = __half22float2(*(const __half2*)&hp2[2 * k2]);
            float2 a3p = __half22float2(*(const __half2*)&hp3[2 * k2]);
            #pragma unroll
            for (int h = 0; h < 2; h++) {
                int k = 2 * k2 + h;
                float a0 = h ? a0p.y : a0p.x;
                float a1 = h ? a1p.y : a1p.x;
                float a2 = h ? a2p.y : a2p.x;
                float a3 = h ? a3p.y : a3p.x;
                float4 wA = *(const float4*)&W2s[k * HID + 8 * fg];
                float4 wB = *(const float4*)&W2s[k * HID + 8 * fg + 4];
                o[0][0] = fmaf(a0, wA.x, o[0][0]); o[0][1] = fmaf(a0, wA.y, o[0][1]);
                o[0][2] = fmaf(a0, wA.z, o[0][2]); o[0][3] = fmaf(a0, wA.w, o[0][3]);
                o[0][4] = fmaf(a0, wB.x, o[0][4]); o[0][5] = fmaf(a0, wB.y, o[0][5]);
                o[0][6] = fmaf(a0, wB.z, o[0][6]); o[0][7] = fmaf(a0, wB.w, o[0][7]);
                o[1][0] = fmaf(a1, wA.x, o[1][0]); o[1][1] = fmaf(a1, wA.y, o[1][1]);
                o[1][2] = fmaf(a1, wA.z, o[1][2]); o[1][3] = fmaf(a1, wA.w, o[1][3]);
                o[1][4] = fmaf(a1, wB.x, o[1][4]); o[1][5] = fmaf(a1, wB.y, o[1][5]);
                o[1][6] = fmaf(a1, wB.z, o[1][6]); o[1][7] = fmaf(a1, wB.w, o[1][7]);
                o[2][0] = fmaf(a2, wA.x, o[2][0]); o[2][1] = fmaf(a2, wA.y, o[2][1]);
                o[2][2] = fmaf(a2, wA.z, o[2][2]); o[2][3] = fmaf(a2, wA.w, o[2][3]);
                o[2][4] = fmaf(a2, wB.x, o[2][4]); o[2][5] = fmaf(a2, wB.y, o[2][5]);
                o[2][6] = fmaf(a2, wB.z, o[2][6]); o[2][7] = fmaf(a2, wB.w, o[2][7]);
                o[3][0] = fmaf(a3, wA.x, o[3][0]); o[3][1] = fmaf(a3, wA.y, o[3][1]);
                o[3][2] = fmaf(a3, wA.z, o[3][2]); o[3][3] = fmaf(a3, wA.w, o[3][3]);
                o[3][4] = fmaf(a3, wB.x, o[3][4]); o[3][5] = fmaf(a3, wB.y, o[3][5]);
                o[3][6] = fmaf(a3, wB.z, o[3][6]); o[3][7] = fmaf(a3, wB.w, o[3][7]);
            }
        }
        #pragma unroll
        for (int i = 0; i < 4; i++) {
            int n = tile * TILE2 + rg * 4 + i;
            if (n < NN) {
                #pragma unroll
                for (int j = 0; j < 8; j++)
                    pool8[j] += fmaxf(o[i][j], 0.f);
            }
        }
        __syncthreads();   // hs/es reused next tile
    }

    // -------- final pool reduction (reuse hs as float scratch) --------
    float* hsf = (float*)hs;   // 32*64 floats = 8 KB
    #pragma unroll
    for (int j = 0; j < 8; j++)
        hsf[rg * HID + 8 * fg + j] = pool8[j];
    __syncthreads();
    if (tid < HID) {
        float s = 0.f;
        #pragma unroll 8
        for (int r = 0; r < 32; r++) s += hsf[r * HID + tid];
        atomicAdd(&g_pool[tid], s);
    }

    // -------- last block: final FC output + state reset for next replay ----
    if (tid == 0) {
        __threadfence();
        int t = atomicAdd(&g_done, 1);
        sh_last = (t == gridDim.x - 1);
    }
    __syncthreads();
    if (sh_last) {
        float s = 0.f;
        if (tid < 32) {
            s = g_pool[tid] * __ldg(&Wfc[tid]) + g_pool[tid + 32] * __ldg(&Wfc[tid + 32]);
            #pragma unroll
            for (int o2 = 16; o2 > 0; o2 >>= 1) s += __shfl_down_sync(0xffffffffu, s, o2);
        }
        __syncthreads();               // all reads of g_pool done
        if (tid < HID) g_pool[tid] = 0.f;
        if (tid == 0) {
            g_done = 0;
            out[0] = s * (1.0f / NN) + __ldg(&bfc[0]);
        }
    }
}

// ---------------- launch ----------------
extern "C" void kernel_launch(void* const* d_in, const int* in_sizes, int n_in,
                              void* d_out, int out_size) {
    const float2* x2    = (const float2*)d_in[0];
    const void*   edges = d_in[1];
    const float*  W1    = (const float*)d_in[2];
    const float*  b1    = (const float*)d_in[3];
    const float*  W2    = (const float*)d_in[4];
    const float*  b2    = (const float*)d_in[5];
    const float*  Wfc   = (const float*)d_in[6];
    const float*  bfc   = (const float*)d_in[7];
    float* out = (float*)d_out;

    cudaFuncSetAttribute(k_gather2, cudaFuncAttributeMaxDynamicSharedMemorySize,
                         SM_TOT);

    const int T = 256;
    k_count<<<(NE / 4 + T - 1) / T, T>>>(edges);
    k_scan<<<NBLK1, SCAN_B>>>(x2);
    k_scatter<<<(NE / 4 + T - 1) / T, T>>>(edges);
    k_h1p<<<(NN * 4 + T - 1) / T, T>>>(W1, b1);
    k_gather2<<<NT2, T, SM_TOT>>>(W2, b2, Wfc, bfc, out);
}